// round 8
// baseline (speedup 1.0000x reference)
#include <cuda_runtime.h>
#include <math.h>
#include <stdint.h>

#define N 2048
#define H 64

typedef unsigned long long ull;

__device__ float g_dA[N];
__device__ float g_h[N*H];
__device__ float g_hn[N*H];
__device__ float g_hd[N*H];
__device__ float g_hsq[N];
__device__ ull   g_cand[N*16];
__device__ int   g_idx[N*4];
__device__ float g_cval[N*4];
__device__ float g_dc[N];
__device__ float g_Z1s[N*2*H];
__device__ float g_Z1f[N*2*H];
__device__ float g_part[8*N*2*H];
__device__ float g_zf[N*H], g_zt[N*H], g_zcf[N*H], g_zct[N*H];
__device__ float g_Lcf[N*H], g_Lct[N*H];
__device__ double g_G[128*128];
__device__ double g_M1[64*64];
__device__ double g_M2[64*64];
__device__ unsigned int g_ticket;

__device__ __forceinline__ float leaky_f(float v){ return v > 0.f ? v : 0.1f*v; }

__device__ __forceinline__ unsigned int fmap(float v){
  unsigned int u = __float_as_uint(v);
  return (u & 0x80000000u) ? ~u : (u | 0x80000000u);
}

__device__ __forceinline__ void top4_insert(ull* t, ull key){
  if (key > t[3]) {
    t[3] = key;
    ull tmp;
    if (t[3] > t[2]) { tmp = t[2]; t[2] = t[3]; t[3] = tmp; }
    if (t[2] > t[1]) { tmp = t[1]; t[1] = t[2]; t[2] = tmp; }
    if (t[1] > t[0]) { tmp = t[0]; t[0] = t[1]; t[1] = tmp; }
  }
}

__device__ __forceinline__ ull pk2(float lo, float hi){
  ull r;
  asm("mov.b64 %0, {%1, %2};" : "=l"(r) : "f"(lo), "f"(hi));
  return r;
}
__device__ __forceinline__ void upk2(ull v, float& lo, float& hi){
  asm("mov.b64 {%0, %1}, %2;" : "=f"(lo), "=f"(hi) : "l"(v));
}
__device__ __forceinline__ ull ffma2(ull a, ull b, ull c){
  ull r;
  asm("fma.rn.f32x2 %0, %1, %2, %3;" : "=l"(r) : "l"(a), "l"(b), "l"(c));
  return r;
}

// ============ 1. fused: rowsum(A) + h = leaky(x@W1^T+b1) + hn/hd/hsq ============
__global__ __launch_bounds__(256) void k_pre(const float* __restrict__ A,
                                             const float* __restrict__ x,
                                             const float* __restrict__ W1,
                                             const float* __restrict__ b1){
  __shared__ float Ws[64][129];
  __shared__ float xs[16][128];
  __shared__ float hs[16][65];
  __shared__ float ss[16];
  __shared__ float das[16];
  int tid = threadIdx.x;
  int base = blockIdx.x * 16;
  for (int e = tid; e < 64*128; e += 256) Ws[e>>7][e&127] = W1[e];
  for (int e = tid; e < 16*128; e += 256) xs[e>>7][e&127] = x[(size_t)base*128 + e];
  {
    int w = tid >> 5, lane = tid & 31;
    int r0 = base + w*2;
    const float* p0 = A + (size_t)r0*N;
    const float* p1 = p0 + N;
    float s0 = 0.f, s1 = 0.f;
    for (int i = lane; i < N; i += 32){ s0 += p0[i]; s1 += p1[i]; }
    for (int o = 16; o > 0; o >>= 1){
      s0 += __shfl_down_sync(0xffffffffu, s0, o);
      s1 += __shfl_down_sync(0xffffffffu, s1, o);
    }
    if (lane == 0){
      float d0 = rsqrtf(s0 + 1e-10f), d1 = rsqrtf(s1 + 1e-10f);
      das[w*2] = d0; das[w*2+1] = d1;
      g_dA[r0] = d0; g_dA[r0+1] = d1;
    }
  }
  __syncthreads();
  int o = tid & 63, rg = tid >> 6;
  float hv[4];
  #pragma unroll
  for (int rr = 0; rr < 4; rr++){
    int rl = rg*4 + rr;
    float a = b1[o];
    #pragma unroll 16
    for (int d = 0; d < 128; d++) a = fmaf(Ws[o][d], xs[rl][d], a);
    hv[rr] = leaky_f(a);
    hs[rl][o] = hv[rr];
  }
  __syncthreads();
  if (tid < 16){
    float s = 0.f;
    #pragma unroll 8
    for (int d = 0; d < 64; d++) s = fmaf(hs[tid][d], hs[tid][d], s);
    ss[tid] = s;
    g_hsq[base + tid] = s;
  }
  __syncthreads();
  #pragma unroll
  for (int rr = 0; rr < 4; rr++){
    int rl = rg*4 + rr, row = base + rl;
    float rn = rsqrtf(ss[rl]);
    float v = hv[rr];
    g_h [row*64 + o] = v;
    g_hn[row*64 + o] = v*rn + 1e-10f;
    g_hd[row*64 + o] = v*das[rl];
  }
}

// ============ shared role: split-K GEMM over A, FFMA2, reg-staged prefetch ============
template<int C>
__device__ __forceinline__ void gemm_role(const float* __restrict__ A,
                                          const float* __restrict__ B,
                                          int rowblk, int ksplit, float* smem){
  constexpr int CPT = C / 16;     // cols per thread (8 or 4)
  constexpr int BLD = C / 8;      // B elems per thread per tile
  float* As = smem;               // [32][68] k-major, rows
  float* Bs = smem + 32*68;       // [32][C+4]
  int tid = threadIdx.x;
  int rowbase = rowblk * 64;
  int kb0 = ksplit * 256;
  int r0 = (tid >> 4) * 4, c0 = (tid & 15) * CPT;
  ull acc[4][CPT/2];
  #pragma unroll
  for (int i = 0; i < 4; i++)
    #pragma unroll
    for (int j = 0; j < CPT/2; j++) acc[i][j] = 0ull;
  float ra[8], rb[BLD];
  #pragma unroll
  for (int i = 0; i < 8; i++){
    int e = tid + i*256;
    ra[i] = A[(size_t)(rowbase + (e>>5))*N + kb0 + (e&31)];
  }
  #pragma unroll
  for (int i = 0; i < BLD; i++){
    int e = tid + i*256;
    rb[i] = B[(kb0 + e/C)*C + (e%C)];
  }
  for (int t = 0; t < 8; t++){
    __syncthreads();
    #pragma unroll
    for (int i = 0; i < 8; i++){
      int e = tid + i*256;
      As[(e&31)*68 + (e>>5)] = ra[i];
    }
    #pragma unroll
    for (int i = 0; i < BLD; i++){
      int e = tid + i*256;
      Bs[(e/C)*(C+4) + (e%C)] = rb[i];
    }
    __syncthreads();
    if (t < 7){
      int kn = kb0 + (t+1)*32;
      #pragma unroll
      for (int i = 0; i < 8; i++){
        int e = tid + i*256;
        ra[i] = A[(size_t)(rowbase + (e>>5))*N + kn + (e&31)];
      }
      #pragma unroll
      for (int i = 0; i < BLD; i++){
        int e = tid + i*256;
        rb[i] = B[(kn + e/C)*C + (e%C)];
      }
    }
    #pragma unroll 4
    for (int kk = 0; kk < 32; kk++){
      float4 a4 = *(const float4*)&As[kk*68 + r0];
      ull a[4] = {pk2(a4.x,a4.x), pk2(a4.y,a4.y), pk2(a4.z,a4.z), pk2(a4.w,a4.w)};
      #pragma unroll
      for (int j4 = 0; j4 < CPT/4; j4++){
        ulonglong2 bv = *(const ulonglong2*)&Bs[kk*(C+4) + c0 + j4*4];
        #pragma unroll
        for (int i = 0; i < 4; i++){
          acc[i][j4*2]   = ffma2(a[i], bv.x, acc[i][j4*2]);
          acc[i][j4*2+1] = ffma2(a[i], bv.y, acc[i][j4*2+1]);
        }
      }
    }
  }
  float* dst = g_part + (size_t)ksplit * N * C;
  #pragma unroll
  for (int i = 0; i < 4; i++)
    #pragma unroll
    for (int j = 0; j < CPT/2; j++){
      float lo, hi;
      upk2(acc[i][j], lo, hi);
      dst[(rowbase + r0 + i)*C + c0 + 2*j]     = lo;
      dst[(rowbase + r0 + i)*C + c0 + 2*j + 1] = hi;
    }
}

// ============ 2. stage1: heat-top4 (256) || gemmA<64> (256) ============
__global__ __launch_bounds__(256) void k_stage1(const float* __restrict__ A){
  __shared__ __align__(16) float smem[6624];
  int b = blockIdx.x, tid = threadIdx.x;
  if (b < 256){
    float* As  = smem;              // [64 d][34 r]
    float* Bs  = smem + 2176;       // [64 d][68 j]
    float* asq = smem + 6528;       // 32
    float* bsq = asq + 32;          // 64
    int rowbase = (b & 63) * 32;
    int jsplit  = b >> 6;
    int jbase   = jsplit * 512;
    int r0 = (tid >> 4) * 2, c0 = (tid & 15) * 4;
    #pragma unroll
    for (int i = 0; i < 8; i++){
      int e = tid + i*256;
      As[(e & 63)*34 + (e >> 6)] = g_h[(rowbase + (e >> 6))*64 + (e & 63)];
    }
    if (tid < 32) asq[tid] = g_hsq[rowbase + tid];
    float rb[16]; float rq;
    #pragma unroll
    for (int i = 0; i < 16; i++){
      int e = tid + i*256;
      rb[i] = g_h[(jbase + (e >> 6))*64 + (e & 63)];
    }
    rq = (tid < 64) ? g_hsq[jbase + tid] : 0.f;
    __syncthreads();
    float asqr0 = asq[r0], asqr1 = asq[r0+1];
    ull t[2][4];
    #pragma unroll
    for (int i = 0; i < 2; i++)
      #pragma unroll
      for (int q = 0; q < 4; q++) t[i][q] = 0ull;
    for (int tile = 0; tile < 8; tile++){
      int jc = jbase + tile*64;
      __syncthreads();
      #pragma unroll
      for (int i = 0; i < 16; i++){
        int e = tid + i*256;
        Bs[(e & 63)*68 + (e >> 6)] = rb[i];
      }
      if (tid < 64) bsq[tid] = rq;
      __syncthreads();
      if (tile < 7){
        int jn = jc + 64;
        #pragma unroll
        for (int i = 0; i < 16; i++){
          int e = tid + i*256;
          rb[i] = g_h[(jn + (e >> 6))*64 + (e & 63)];
        }
        rq = (tid < 64) ? g_hsq[jn + tid] : 0.f;
      }
      ull acc[2][2] = {{0ull,0ull},{0ull,0ull}};
      #pragma unroll 8
      for (int kk = 0; kk < 64; kk++){
        float2 a2 = *(const float2*)&As[kk*34 + r0];
        ull avx = pk2(a2.x, a2.x);
        ull avy = pk2(a2.y, a2.y);
        ulonglong2 bv = *(const ulonglong2*)&Bs[kk*68 + c0];
        acc[0][0] = ffma2(avx, bv.x, acc[0][0]);
        acc[0][1] = ffma2(avx, bv.y, acc[0][1]);
        acc[1][0] = ffma2(avy, bv.x, acc[1][0]);
        acc[1][1] = ffma2(avy, bv.y, acc[1][1]);
      }
      float bq[4] = {bsq[c0], bsq[c0+1], bsq[c0+2], bsq[c0+3]};
      #pragma unroll
      for (int i = 0; i < 2; i++){
        float asqr = i ? asqr1 : asqr0;
        float d0, d1, d2, d3;
        upk2(acc[i][0], d0, d1);
        upk2(acc[i][1], d2, d3);
        float dd[4] = {d0, d1, d2, d3};
        #pragma unroll
        for (int j = 0; j < 4; j++){
          float dist = asqr + bq[j] - 2.f*dd[j] + 6.4e-9f;
          int jg = jc + c0 + j;
          ull key = ((ull)fmap(-dist) << 32) | (unsigned int)(2047 - jg);
          top4_insert(t[i], key);
        }
      }
    }
    __syncthreads();
    ull* cand = (ull*)smem;   // 32*64 ull = 16KB alias
    #pragma unroll
    for (int i = 0; i < 2; i++)
      #pragma unroll
      for (int q = 0; q < 4; q++)
        cand[(r0 + i)*64 + c0 + q] = t[i][q];
    __syncthreads();
    if (tid < 32){
      ull m[4] = {0ull,0ull,0ull,0ull};
      for (int e = 0; e < 64; e++) top4_insert(m, cand[tid*64 + e]);
      #pragma unroll
      for (int q = 0; q < 4; q++)
        g_cand[(rowbase + tid)*16 + jsplit*4 + q] = m[q];
    }
  } else {
    int bb = b - 256;
    gemm_role<64>(A, g_hd, bb & 31, bb >> 5, smem);
  }
}

// ============ z-layer roles ============
__device__ __forceinline__ void z1t_role(int row4, const float* __restrict__ WT1, const float* __restrict__ bT1,
                                         const float* __restrict__ WC1, const float* __restrict__ bC1, float* smem){
  float* Wa_ = smem;            // 64x65
  float* Wb_ = smem + 4160;     // 64x65
  float* ps  = smem + 8320;     // 4x65
  int tid = threadIdx.x; int sub = tid >> 6; int o = tid & 63;
  for (int e = tid; e < 4096; e += 256){
    Wa_[(e>>6)*65 + (e&63)] = WT1[e];
    Wb_[(e>>6)*65 + (e&63)] = WC1[e];
  }
  int row = row4*4 + sub;
  float p = 0.f;
  #pragma unroll
  for (int s = 0; s < 8; s++) p += g_part[(size_t)s*N*64 + row*64 + o];
  float da = g_dA[row];
  ps[sub*65 + o] = da * p;
  __syncthreads();
  float a1 = bT1[o], a2 = bC1[o];
  #pragma unroll 16
  for (int d = 0; d < 64; d++){
    float m = ps[sub*65 + d];
    a1 = fmaf(Wa_[o*65 + d], m, a1);
    a2 = fmaf(Wb_[o*65 + d], m, a2);
  }
  g_Z1s[row*128 + o]      = da * leaky_f(a1);
  g_Z1s[row*128 + 64 + o] = da * leaky_f(a2);
}

__device__ __forceinline__ void cos_role(int blk){
  int w = threadIdx.x >> 5;
  int lane = threadIdx.x & 31;
  int row = blk * 8 + w;
  ull t[4] = {0ull,0ull,0ull,0ull};
  if (lane < 16) t[0] = g_cand[row*16 + lane];
  #pragma unroll
  for (int off = 8; off >= 1; off >>= 1){
    ull r0 = __shfl_down_sync(0xffffffffu, t[0], off);
    ull r1 = __shfl_down_sync(0xffffffffu, t[1], off);
    ull r2 = __shfl_down_sync(0xffffffffu, t[2], off);
    ull r3 = __shfl_down_sync(0xffffffffu, t[3], off);
    top4_insert(t, r0); top4_insert(t, r1);
    top4_insert(t, r2); top4_insert(t, r3);
  }
  int idx[4];
  #pragma unroll
  for (int q = 0; q < 4; q++){
    ull k = __shfl_sync(0xffffffffu, t[q], 0);
    idx[q] = 2047 - (int)(unsigned int)(k & 0xFFFFFFFFull);
  }
  if (lane == 0){
    #pragma unroll
    for (int q = 0; q < 4; q++) g_idx[row*4 + q] = idx[q];
  }
  float c[4];
  #pragma unroll
  for (int q = 0; q < 4; q++){
    int j = idx[q];
    float s = g_hn[row*64 + lane]      * g_hn[j*64 + lane]
            + g_hn[row*64 + 32 + lane] * g_hn[j*64 + 32 + lane];
    for (int o = 16; o > 0; o >>= 1) s += __shfl_down_sync(0xffffffffu, s, o);
    c[q] = s;
  }
  if (lane == 0){
    float rs = c[0] + c[1] + c[2] + c[3];
    g_dc[row] = rsqrtf(rs + 1e-10f);
    #pragma unroll
    for (int q = 0; q < 4; q++) g_cval[row*4 + q] = c[q];
  }
}

// ============ 3. stage2: cos (256) || z1t (512) ============
__global__ __launch_bounds__(256) void k_stage2(const float* __restrict__ WT1, const float* __restrict__ bT1,
                                                const float* __restrict__ WC1, const float* __restrict__ bC1){
  __shared__ __align__(16) float smem[8580];
  int b = blockIdx.x;
  if (b < 256) cos_role(b);
  else z1t_role(b - 256, WT1, bT1, WC1, bC1, smem);
}

// slim z1f: W via __ldg (stage3 co-resides with gemm128)
__device__ __forceinline__ void z1f_role(int row4, const float* __restrict__ WF1, const float* __restrict__ bF1,
                                         const float* __restrict__ WC1, const float* __restrict__ bC1, float* smem){
  float* ms = smem;   // 4x65
  int tid = threadIdx.x; int sub = tid >> 6; int o = tid & 63;
  int row = row4*4 + sub;
  float dci = g_dc[row];
  float m = 0.f;
  #pragma unroll
  for (int t = 0; t < 4; t++){
    int j = g_idx[row*4 + t];
    float coef = g_cval[row*4 + t] * dci * g_dc[j];
    m = fmaf(coef, g_h[j*64 + o], m);
  }
  ms[sub*65 + o] = m;
  __syncthreads();
  float a1 = bF1[o], a2 = bC1[o];
  #pragma unroll 16
  for (int d = 0; d < 64; d++){
    float v = ms[sub*65 + d];
    a1 = fmaf(__ldg(&WF1[o*64 + d]), v, a1);
    a2 = fmaf(__ldg(&WC1[o*64 + d]), v, a2);
  }
  g_Z1f[row*128 + o]      = leaky_f(a1);
  g_Z1f[row*128 + 64 + o] = leaky_f(a2);
}

// ============ 4. stage3: gemmA<128> (256) || z1f (512) ============
__global__ __launch_bounds__(256) void k_stage3(const float* __restrict__ A,
                                                const float* __restrict__ WF1, const float* __restrict__ bF1,
                                                const float* __restrict__ WC1, const float* __restrict__ bC1){
  __shared__ __align__(16) float smem[6400];
  int b = blockIdx.x;
  if (b < 256) gemm_role<128>(A, g_Z1s, b & 31, b >> 5, smem);
  else z1f_role(b - 256, WF1, bF1, WC1, bC1, smem);
}

__device__ __forceinline__ void z2t_role(int row4, const float* __restrict__ WT2, const float* __restrict__ bT2,
                                         const float* __restrict__ WC2, const float* __restrict__ bC2, float* smem){
  float* Wa_ = smem;
  float* Wb_ = smem + 4160;
  float* ps  = smem + 8320;   // 4x130
  float* red = smem + 8840;   // 4x64
  int tid = threadIdx.x; int sub = tid >> 6; int o = tid & 63;
  for (int e = tid; e < 4096; e += 256){
    Wa_[(e>>6)*65 + (e&63)] = WT2[e];
    Wb_[(e>>6)*65 + (e&63)] = WC2[e];
  }
  int row = row4*4 + sub;
  float da = g_dA[row];
  float pA = 0.f, pB = 0.f;
  #pragma unroll
  for (int s = 0; s < 8; s++){
    pA += g_part[(size_t)s*N*128 + row*128 + o];
    pB += g_part[(size_t)s*N*128 + row*128 + 64 + o];
  }
  ps[sub*130 + o]      = da * pA;
  ps[sub*130 + 64 + o] = da * pB;
  __syncthreads();
  float a1 = bT2[o], a2 = bC2[o];
  #pragma unroll 16
  for (int d = 0; d < 64; d++){
    a1 = fmaf(Wa_[o*65 + d], ps[sub*130 + d],      a1);
    a2 = fmaf(Wb_[o*65 + d], ps[sub*130 + 64 + d], a2);
  }
  float zt  = leaky_f(a1);
  float zct = leaky_f(a2);
  g_zt [row*64 + o] = zt;
  g_zct[row*64 + o] = zct;
  red[sub*64 + o] = zct*zct;
  __syncthreads();
  for (int off = 32; off > 0; off >>= 1){
    if (o < off) red[sub*64 + o] += red[sub*64 + o + off];
    __syncthreads();
  }
  float mn = sqrtf(red[sub*64] * 0.015625f) + 1e-10f;
  g_Lct[row*64 + o] = zct / mn;
}

__device__ __forceinline__ void z2f_role(int row4, const float* __restrict__ WF2, const float* __restrict__ bF2,
                                         const float* __restrict__ WC2, const float* __restrict__ bC2, float* smem){
  float* Wa_ = smem;
  float* Wb_ = smem + 4160;
  float* ms  = smem + 8320;   // 4x130
  float* red = smem + 8840;   // 4x64
  int tid = threadIdx.x; int sub = tid >> 6; int o = tid & 63;
  for (int e = tid; e < 4096; e += 256){
    Wa_[(e>>6)*65 + (e&63)] = WF2[e];
    Wb_[(e>>6)*65 + (e&63)] = WC2[e];
  }
  int row = row4*4 + sub;
  float dci = g_dc[row];
  float mf = 0.f, mc = 0.f;
  #pragma unroll
  for (int t = 0; t < 4; t++){
    int j = g_idx[row*4 + t];
    float coef = g_cval[row*4 + t] * dci * g_dc[j];
    mf = fmaf(coef, g_Z1f[j*128 + o],      mf);
    mc = fmaf(coef, g_Z1f[j*128 + 64 + o], mc);
  }
  ms[sub*130 + o]      = mf;
  ms[sub*130 + 64 + o] = mc;
  __syncthreads();
  float a1 = bF2[o], a2 = bC2[o];
  #pragma unroll 16
  for (int d = 0; d < 64; d++){
    a1 = fmaf(Wa_[o*65 + d], ms[sub*130 + d],      a1);
    a2 = fmaf(Wb_[o*65 + d], ms[sub*130 + 64 + d], a2);
  }
  float zf  = leaky_f(a1);
  float zcf = leaky_f(a2);
  g_zf [row*64 + o] = zf;
  g_zcf[row*64 + o] = zcf;
  red[sub*64 + o] = zcf*zcf;
  __syncthreads();
  for (int off = 32; off > 0; off >>= 1){
    if (o < off) red[sub*64 + o] += red[sub*64 + o + off];
    __syncthreads();
  }
  float mn = sqrtf(red[sub*64] * 0.015625f) + 1e-10f;
  g_Lcf[row*64 + o] = zcf / mn;
}

// ============ 5. stage4: z2t (512) || z2f (512) ============
__global__ __launch_bounds__(256) void k_stage4(const float* __restrict__ WT2, const float* __restrict__ bT2,
                                                const float* __restrict__ WF2, const float* __restrict__ bF2,
                                                const float* __restrict__ WC2, const float* __restrict__ bC2){
  __shared__ __align__(16) float smem[9096];
  int b = blockIdx.x;
  if (b < 512) z2t_role(b, WT2, bT2, WC2, bC2, smem);
  else z2f_role(b - 512, WF2, bF2, WC2, bC2, smem);
}

// ============ gram role (inline column means for modes 1/2) ============
__device__ __forceinline__ void gram_role(int mode, int bx, int by, float* smem){
  float* As = smem;            // 64x17
  float* Bs = smem + 1088;     // 64x17
  float* mean = smem + 2176;   // 16
  const float *A0, *A1, *B0, *B1; double* out; int cb; int use_mean;
  if (mode == 0){ A0 = g_Lcf; A1 = g_Lct; B0 = g_Lcf; B1 = g_Lct; use_mean = 0; out = g_G; cb = 128; }
  else if (mode == 1){ A0 = g_zt; A1 = 0; B0 = g_zct; B1 = 0; use_mean = 1; out = g_M1; cb = 64; }
  else              { A0 = g_zf; A1 = 0; B0 = g_zcf; B1 = 0; use_mean = 1; out = g_M2; cb = 64; }
  int ci0 = bx * 16, cj0 = by * 16;
  const float* Ap = (ci0 < 64) ? A0 : A1; int ca_off = ci0 & 63;
  const float* Bp = (cj0 < 64) ? B0 : B1; int cb_off = cj0 & 63;
  int tid = threadIdx.x;
  int ty = tid >> 4, tx = tid & 15;
  if (use_mean){
    float s = 0.f;
    for (int r = ty; r < N; r += 16) s += Ap[r*64 + ca_off + tx];
    As[ty*17 + tx] = s;
    __syncthreads();
    if (ty == 0){
      float m = 0.f;
      #pragma unroll
      for (int k = 0; k < 16; k++) m += As[k*17 + tx];
      mean[tx] = m / (float)N;
    }
    __syncthreads();
  }
  double acc = 0.0; float f = 0.f;
  for (int n0 = 0; n0 < N; n0 += 64){
    __syncthreads();
    #pragma unroll
    for (int e = tid; e < 1024; e += 256){
      int r = n0 + (e >> 4);
      float av = Ap[r*64 + ca_off + (e & 15)];
      if (use_mean) av -= mean[e & 15];
      As[(e >> 4)*17 + (e & 15)] = av;
      Bs[(e >> 4)*17 + (e & 15)] = Bp[r*64 + cb_off + (e & 15)];
    }
    __syncthreads();
    #pragma unroll 16
    for (int r2 = 0; r2 < 64; r2++) f = fmaf(As[r2*17 + ty], Bs[r2*17 + tx], f);
    if (((n0 >> 6) & 1) == 1){ acc += (double)f; f = 0.f; }
  }
  out[(ci0 + ty)*cb + cj0 + tx] = acc;
}

__device__ __forceinline__ void att_role(int blk, const float* __restrict__ Wa, const float* __restrict__ ba,
                                         const float* __restrict__ q,  const float* __restrict__ W2,
                                         const float* __restrict__ b2, float* __restrict__ out, float* smem){
  float* Was = smem;            // 64x65
  float* qv  = smem + 4160;     // 64
  float* zsh = smem + 4224;     // 4x3x64
  float* red = smem + 4992;     // 4x64
  float* sv  = smem + 5248;     // 4x3
  float* av  = smem + 5260;     // 4x3
  float* zag = smem + 5272;     // 4x64
  int tid = threadIdx.x; int sub = tid >> 6; int o = tid & 63;
  for (int e = tid; e < 4096; e += 256) Was[(e>>6)*65 + (e&63)] = Wa[e];
  if (tid < 64) qv[tid] = q[tid];
  __syncthreads();
  int row = blk*4 + sub;
  float zfv  = g_zf [row*64 + o];
  float ztv  = g_zt [row*64 + o];
  float zcv  = 0.5f*(g_zcf[row*64 + o] + g_zct[row*64 + o]);
  zsh[(sub*3 + 0)*64 + o] = zfv;
  zsh[(sub*3 + 1)*64 + o] = ztv;
  zsh[(sub*3 + 2)*64 + o] = zcv;
  __syncthreads();
  #pragma unroll
  for (int kk = 0; kk < 3; kk++){
    float t = ba[o];
    #pragma unroll 16
    for (int d = 0; d < 64; d++) t = fmaf(Was[o*65 + d], zsh[(sub*3 + kk)*64 + d], t);
    t = tanhf(t) * qv[o];
    red[sub*64 + o] = t;
    __syncthreads();
    if (o < 32) red[sub*64 + o] += red[sub*64 + o + 32];
    __syncthreads();
    if (o < 32){
      float s = red[sub*64 + o];
      for (int off = 16; off > 0; off >>= 1) s += __shfl_down_sync(0xffffffffu, s, off);
      if (o == 0) sv[sub*3 + kk] = s;
    }
    __syncthreads();
  }
  if (o == 0){
    float m = fmaxf(sv[sub*3], fmaxf(sv[sub*3+1], sv[sub*3+2]));
    float e0 = expf(sv[sub*3]-m), e1 = expf(sv[sub*3+1]-m), e2 = expf(sv[sub*3+2]-m);
    float inv = 1.f/(e0+e1+e2);
    av[sub*3] = e0*inv; av[sub*3+1] = e1*inv; av[sub*3+2] = e2*inv;
  }
  __syncthreads();
  zag[sub*64 + o] = av[sub*3]*zfv + av[sub*3+1]*ztv + av[sub*3+2]*zcv;
  __syncthreads();
  if (o < 7){
    float v = b2[o];
    #pragma unroll 16
    for (int d = 0; d < 64; d++) v = fmaf(W2[o*64 + d], zag[sub*64 + d], v);
    out[row*7 + o] = v;
  }
}

// ============ 6. stage5: gram x3 (96) || att (512), fused final via ticket ============
__global__ __launch_bounds__(256) void k_stage5(const float* __restrict__ Wa, const float* __restrict__ ba,
                                                const float* __restrict__ q,  const float* __restrict__ W2,
                                                const float* __restrict__ b2, float* __restrict__ out){
  __shared__ __align__(16) float smem[5536];
  __shared__ unsigned int s_last;
  int b = blockIdx.x;
  int tid = threadIdx.x;
  if (b < 96){
    if (b < 64)      gram_role(0, b >> 3, b & 7, smem);
    else if (b < 80) gram_role(1, (b - 64) >> 2, (b - 64) & 3, smem);
    else             gram_role(2, (b - 80) >> 2, (b - 80) & 3, smem);
    __threadfence();
    __syncthreads();
    if (tid == 0) s_last = (atomicAdd(&g_ticket, 1u) == 95u) ? 1u : 0u;
    __syncthreads();
    if (s_last){
      if (tid == 0) g_ticket = 0u;
      __threadfence();
      double lc = 0.0, ld = 0.0;
      for (int e = tid; e < 128*128; e += 256){
        int a = e >> 7, bb = e & 127;
        double s = ((a < 64) == (bb < 64)) ? 1.0 : -1.0;
        double g = g_G[e];
        lc += s * g * g;
      }
      for (int e = tid; e < 64*64; e += 256){
        double m1 = g_M1[e]; ld += m1*m1;
        double m2 = g_M2[e]; ld += m2*m2;
      }
      double* s1 = (double*)smem;
      double* s2 = s1 + 256;
      s1[tid] = lc; s2[tid] = ld; __syncthreads();
      for (int o = 128; o > 0; o >>= 1){
        if (tid < o){ s1[tid] += s1[tid + o]; s2[tid] += s2[tid + o]; }
        __syncthreads();
      }
      if (tid == 0){
        out[N*7]     = (float)(s1[0] / ((double)N * (double)N));
        out[N*7 + 1] = (float)(s2[0] / (2047.0 * 2047.0));
      }
    }
  } else {
    att_role(b - 96, Wa, ba, q, W2, b2, out, smem);
  }
}

extern "C" void kernel_launch(void* const* d_in, const int* in_sizes, int n_in,
                              void* d_out, int out_size){
  const float* x   = (const float*)d_in[0];
  const float* A   = (const float*)d_in[1];
  const float* W1  = (const float*)d_in[3];
  const float* b1  = (const float*)d_in[4];
  const float* WF1 = (const float*)d_in[5];
  const float* bF1 = (const float*)d_in[6];
  const float* WF2 = (const float*)d_in[7];
  const float* bF2 = (const float*)d_in[8];
  const float* WT1 = (const float*)d_in[9];
  const float* bT1 = (const float*)d_in[10];
  const float* WT2 = (const float*)d_in[11];
  const float* bT2 = (const float*)d_in[12];
  const float* WC1 = (const float*)d_in[13];
  const float* bC1 = (const float*)d_in[14];
  const float* WC2 = (const float*)d_in[15];
  const float* bC2 = (const float*)d_in[16];
  const float* Wa  = (const float*)d_in[17];
  const float* ba  = (const float*)d_in[18];
  const float* q   = (const float*)d_in[19];
  const float* W2  = (const float*)d_in[20];
  const float* b2  = (const float*)d_in[21];
  float* out = (float*)d_out;

  k_pre   <<<N/16, 256>>>(A, x, W1, b1);
  k_stage1<<<512,  256>>>(A);
  k_stage2<<<768,  256>>>(WT1, bT1, WC1, bC1);
  k_stage3<<<768,  256>>>(A, WF1, bF1, WC1, bC1);
  k_stage4<<<1024, 256>>>(WT2, bT2, WF2, bF2, WC2, bC2);
  k_stage5<<<608,  256>>>(Wa, ba, q, W2, b2, out);
}

// round 9
// speedup vs baseline: 1.0605x; 1.0605x over previous
#include <cuda_runtime.h>
#include <math.h>
#include <stdint.h>

#define N 2048
#define H 64

typedef unsigned long long ull;

__device__ float g_dA[N];
__device__ float g_h[N*H];
__device__ float g_hn[N*H];
__device__ float g_hd[N*H];
__device__ float g_hsq[N];
__device__ ull   g_cand[N*16];
__device__ int   g_idx[N*4];
__device__ float g_cval[N*4];
__device__ float g_dc[N];
__device__ float g_Z1s[N*2*H];
__device__ float g_Z1f[N*2*H];
__device__ float g_part[8*N*2*H];
__device__ float g_zf[N*H], g_zt[N*H], g_zcf[N*H], g_zct[N*H];
__device__ float g_Lcf[N*H], g_Lct[N*H];
__device__ double g_G[128*128];
__device__ double g_M1[64*64];
__device__ double g_M2[64*64];
__device__ unsigned int g_ticket;

__device__ __forceinline__ float leaky_f(float v){ return v > 0.f ? v : 0.1f*v; }

__device__ __forceinline__ unsigned int fmap(float v){
  unsigned int u = __float_as_uint(v);
  return (u & 0x80000000u) ? ~u : (u | 0x80000000u);
}

__device__ __forceinline__ void top4_insert(ull* t, ull key){
  if (key > t[3]) {
    t[3] = key;
    ull tmp;
    if (t[3] > t[2]) { tmp = t[2]; t[2] = t[3]; t[3] = tmp; }
    if (t[2] > t[1]) { tmp = t[1]; t[1] = t[2]; t[2] = tmp; }
    if (t[1] > t[0]) { tmp = t[0]; t[0] = t[1]; t[1] = tmp; }
  }
}

__device__ __forceinline__ ull pk2(float lo, float hi){
  ull r;
  asm("mov.b64 %0, {%1, %2};" : "=l"(r) : "f"(lo), "f"(hi));
  return r;
}
__device__ __forceinline__ void upk2(ull v, float& lo, float& hi){
  asm("mov.b64 {%0, %1}, %2;" : "=f"(lo), "=f"(hi) : "l"(v));
}
__device__ __forceinline__ ull ffma2(ull a, ull b, ull c){
  ull r;
  asm("fma.rn.f32x2 %0, %1, %2, %3;" : "=l"(r) : "l"(a), "l"(b), "l"(c));
  return r;
}

// ============ 1. fused: rowsum(A) + h + hn/hd/hsq ============
__global__ __launch_bounds__(256) void k_pre(const float* __restrict__ A,
                                             const float* __restrict__ x,
                                             const float* __restrict__ W1,
                                             const float* __restrict__ b1){
  __shared__ float Ws[64][129];
  __shared__ float xs[16][128];
  __shared__ float hs[16][65];
  __shared__ float ss[16];
  __shared__ float das[16];
  int tid = threadIdx.x;
  int base = blockIdx.x * 16;
  for (int e = tid; e < 64*128; e += 256) Ws[e>>7][e&127] = W1[e];
  for (int e = tid; e < 16*128; e += 256) xs[e>>7][e&127] = x[(size_t)base*128 + e];
  {
    int w = tid >> 5, lane = tid & 31;
    int r0 = base + w*2;
    const float* p0 = A + (size_t)r0*N;
    const float* p1 = p0 + N;
    float s0 = 0.f, s1 = 0.f;
    for (int i = lane; i < N; i += 32){ s0 += p0[i]; s1 += p1[i]; }
    for (int o = 16; o > 0; o >>= 1){
      s0 += __shfl_down_sync(0xffffffffu, s0, o);
      s1 += __shfl_down_sync(0xffffffffu, s1, o);
    }
    if (lane == 0){
      float d0 = rsqrtf(s0 + 1e-10f), d1 = rsqrtf(s1 + 1e-10f);
      das[w*2] = d0; das[w*2+1] = d1;
      g_dA[r0] = d0; g_dA[r0+1] = d1;
    }
  }
  __syncthreads();
  int o = tid & 63, rg = tid >> 6;
  float hv[4];
  #pragma unroll
  for (int rr = 0; rr < 4; rr++){
    int rl = rg*4 + rr;
    float a = b1[o];
    #pragma unroll 16
    for (int d = 0; d < 128; d++) a = fmaf(Ws[o][d], xs[rl][d], a);
    hv[rr] = leaky_f(a);
    hs[rl][o] = hv[rr];
  }
  __syncthreads();
  if (tid < 16){
    float s = 0.f;
    #pragma unroll 8
    for (int d = 0; d < 64; d++) s = fmaf(hs[tid][d], hs[tid][d], s);
    ss[tid] = s;
    g_hsq[base + tid] = s;
  }
  __syncthreads();
  #pragma unroll
  for (int rr = 0; rr < 4; rr++){
    int rl = rg*4 + rr, row = base + rl;
    float rn = rsqrtf(ss[rl]);
    float v = hv[rr];
    g_h [row*64 + o] = v;
    g_hn[row*64 + o] = v*rn + 1e-10f;
    g_hd[row*64 + o] = v*das[rl];
  }
}

// ============ shared role: split-K GEMM over A, double-buffered, 1 sync/tile ============
template<int C>
__device__ __forceinline__ void gemm_role(const float* __restrict__ A,
                                          const float* __restrict__ B,
                                          int rowblk, int ksplit, float* smem){
  constexpr int CPT = C / 16;      // cols per thread
  constexpr int BPT = C / 16;      // B elems per thread per 16-k tile
  float* Asb[2] = {smem, smem + 1088};                         // [16][68]
  float* Bsb[2] = {smem + 2176, smem + 2176 + 16*(C+4)};       // [16][C+4]
  int tid = threadIdx.x;
  int rowbase = rowblk * 64;
  int kb0 = ksplit * 256;
  int r0 = (tid >> 4) * 4, c0 = (tid & 15) * CPT;
  ull acc[4][CPT/2];
  #pragma unroll
  for (int i = 0; i < 4; i++)
    #pragma unroll
    for (int j = 0; j < CPT/2; j++) acc[i][j] = 0ull;
  float ra[4], rb[BPT];
  #pragma unroll
  for (int i = 0; i < 4; i++){
    int e = tid + i*256;
    ra[i] = A[(size_t)(rowbase + (e>>4))*N + kb0 + (e&15)];
  }
  #pragma unroll
  for (int i = 0; i < BPT; i++){
    int e = tid + i*256;
    rb[i] = B[(kb0 + e/C)*C + (e%C)];
  }
  #pragma unroll
  for (int i = 0; i < 4; i++){
    int e = tid + i*256;
    Asb[0][(e&15)*68 + (e>>4)] = ra[i];
  }
  #pragma unroll
  for (int i = 0; i < BPT; i++){
    int e = tid + i*256;
    Bsb[0][(e/C)*(C+4) + (e%C)] = rb[i];
  }
  __syncthreads();
  for (int t = 0; t < 16; t++){
    int cur = t & 1;
    if (t < 15){
      int kn = kb0 + (t+1)*16;
      #pragma unroll
      for (int i = 0; i < 4; i++){
        int e = tid + i*256;
        ra[i] = A[(size_t)(rowbase + (e>>4))*N + kn + (e&15)];
      }
      #pragma unroll
      for (int i = 0; i < BPT; i++){
        int e = tid + i*256;
        rb[i] = B[(kn + e/C)*C + (e%C)];
      }
    }
    const float* As = Asb[cur];
    const float* Bs = Bsb[cur];
    #pragma unroll
    for (int kk = 0; kk < 16; kk++){
      float4 a4 = *(const float4*)&As[kk*68 + r0];
      ull a[4] = {pk2(a4.x,a4.x), pk2(a4.y,a4.y), pk2(a4.z,a4.z), pk2(a4.w,a4.w)};
      #pragma unroll
      for (int j4 = 0; j4 < CPT/4; j4++){
        ulonglong2 bv = *(const ulonglong2*)&Bs[kk*(C+4) + c0 + j4*4];
        #pragma unroll
        for (int i = 0; i < 4; i++){
          acc[i][j4*2]   = ffma2(a[i], bv.x, acc[i][j4*2]);
          acc[i][j4*2+1] = ffma2(a[i], bv.y, acc[i][j4*2+1]);
        }
      }
    }
    if (t < 15){
      int nxt = 1 - cur;
      #pragma unroll
      for (int i = 0; i < 4; i++){
        int e = tid + i*256;
        Asb[nxt][(e&15)*68 + (e>>4)] = ra[i];
      }
      #pragma unroll
      for (int i = 0; i < BPT; i++){
        int e = tid + i*256;
        Bsb[nxt][(e/C)*(C+4) + (e%C)] = rb[i];
      }
    }
    __syncthreads();
  }
  float* dst = g_part + (size_t)ksplit * N * C;
  #pragma unroll
  for (int i = 0; i < 4; i++)
    #pragma unroll
    for (int j = 0; j < CPT/2; j++){
      float lo, hi;
      upk2(acc[i][j], lo, hi);
      dst[(rowbase + r0 + i)*C + c0 + 2*j]     = lo;
      dst[(rowbase + r0 + i)*C + c0 + 2*j + 1] = hi;
    }
}

// ============ 2. stage1: heat-top4 (256, db) || gemmA<64> (256) ============
__global__ __launch_bounds__(256) void k_stage1(const float* __restrict__ A){
  __shared__ __align__(16) float smem[11040];
  int b = blockIdx.x, tid = threadIdx.x;
  if (b < 256){
    float* As   = smem;                  // [64 d][34 r]
    float* Bsb[2] = {smem + 2176, smem + 6528};   // [64 d][68 j]
    float* asq  = smem + 10880;          // 32
    float* bqb[2] = {smem + 10912, smem + 10976}; // 64 each
    int rowbase = (b & 63) * 32;
    int jsplit  = b >> 6;
    int jbase   = jsplit * 512;
    int r0 = (tid >> 4) * 2, c0 = (tid & 15) * 4;
    #pragma unroll
    for (int i = 0; i < 8; i++){
      int e = tid + i*256;
      As[(e & 63)*34 + (e >> 6)] = g_h[(rowbase + (e >> 6))*64 + (e & 63)];
    }
    if (tid < 32) asq[tid] = g_hsq[rowbase + tid];
    float rb[16], rq;
    #pragma unroll
    for (int i = 0; i < 16; i++){
      int e = tid + i*256;
      rb[i] = g_h[(jbase + (e >> 6))*64 + (e & 63)];
    }
    rq = (tid < 64) ? g_hsq[jbase + tid] : 0.f;
    #pragma unroll
    for (int i = 0; i < 16; i++){
      int e = tid + i*256;
      Bsb[0][(e & 63)*68 + (e >> 6)] = rb[i];
    }
    if (tid < 64) bqb[0][tid] = rq;
    __syncthreads();
    float asqr0 = asq[r0], asqr1 = asq[r0+1];
    ull t[2][4];
    #pragma unroll
    for (int i = 0; i < 2; i++)
      #pragma unroll
      for (int q = 0; q < 4; q++) t[i][q] = 0ull;
    for (int tile = 0; tile < 8; tile++){
      int cur = tile & 1;
      int jc = jbase + tile*64;
      if (tile < 7){
        int jn = jc + 64;
        #pragma unroll
        for (int i = 0; i < 16; i++){
          int e = tid + i*256;
          rb[i] = g_h[(jn + (e >> 6))*64 + (e & 63)];
        }
        rq = (tid < 64) ? g_hsq[jn + tid] : 0.f;
      }
      const float* Bs = Bsb[cur];
      const float* bsq = bqb[cur];
      ull acc[2][2] = {{0ull,0ull},{0ull,0ull}};
      #pragma unroll 8
      for (int kk = 0; kk < 64; kk++){
        float2 a2 = *(const float2*)&As[kk*34 + r0];
        ull avx = pk2(a2.x, a2.x);
        ull avy = pk2(a2.y, a2.y);
        ulonglong2 bv = *(const ulonglong2*)&Bs[kk*68 + c0];
        acc[0][0] = ffma2(avx, bv.x, acc[0][0]);
        acc[0][1] = ffma2(avx, bv.y, acc[0][1]);
        acc[1][0] = ffma2(avy, bv.x, acc[1][0]);
        acc[1][1] = ffma2(avy, bv.y, acc[1][1]);
      }
      float bq[4] = {bsq[c0], bsq[c0+1], bsq[c0+2], bsq[c0+3]};
      #pragma unroll
      for (int i = 0; i < 2; i++){
        float asqr = i ? asqr1 : asqr0;
        float d0, d1, d2, d3;
        upk2(acc[i][0], d0, d1);
        upk2(acc[i][1], d2, d3);
        float dd[4] = {d0, d1, d2, d3};
        #pragma unroll
        for (int j = 0; j < 4; j++){
          float dist = asqr + bq[j] - 2.f*dd[j] + 6.4e-9f;
          int jg = jc + c0 + j;
          ull key = ((ull)fmap(-dist) << 32) | (unsigned int)(2047 - jg);
          top4_insert(t[i], key);
        }
      }
      if (tile < 7){
        int nxt = 1 - cur;
        #pragma unroll
        for (int i = 0; i < 16; i++){
          int e = tid + i*256;
          Bsb[nxt][(e & 63)*68 + (e >> 6)] = rb[i];
        }
        if (tid < 64) bqb[nxt][tid] = rq;
      }
      __syncthreads();
    }
    ull* cand = (ull*)smem;   // 32*64 ull = 16KB alias (safe: all reads done)
    __syncthreads();
    #pragma unroll
    for (int i = 0; i < 2; i++)
      #pragma unroll
      for (int q = 0; q < 4; q++)
        cand[(r0 + i)*64 + c0 + q] = t[i][q];
    __syncthreads();
    if (tid < 32){
      ull m[4] = {0ull,0ull,0ull,0ull};
      for (int e = 0; e < 64; e++) top4_insert(m, cand[tid*64 + e]);
      #pragma unroll
      for (int q = 0; q < 4; q++)
        g_cand[(rowbase + tid)*16 + jsplit*4 + q] = m[q];
    }
  } else {
    int bb = b - 256;
    gemm_role<64>(A, g_hd, bb & 31, bb >> 5, smem);
  }
}

// ============ z-layer roles ============
__device__ __forceinline__ void z1t_role(int row4, const float* __restrict__ WT1, const float* __restrict__ bT1,
                                         const float* __restrict__ WC1, const float* __restrict__ bC1, float* smem){
  float* Wa_ = smem;            // 64x65
  float* Wb_ = smem + 4160;     // 64x65
  float* ps  = smem + 8320;     // 4x65
  int tid = threadIdx.x; int sub = tid >> 6; int o = tid & 63;
  for (int e = tid; e < 4096; e += 256){
    Wa_[(e>>6)*65 + (e&63)] = WT1[e];
    Wb_[(e>>6)*65 + (e&63)] = WC1[e];
  }
  int row = row4*4 + sub;
  float p = 0.f;
  #pragma unroll
  for (int s = 0; s < 8; s++) p += g_part[(size_t)s*N*64 + row*64 + o];
  float da = g_dA[row];
  ps[sub*65 + o] = da * p;
  __syncthreads();
  float a1 = bT1[o], a2 = bC1[o];
  #pragma unroll 16
  for (int d = 0; d < 64; d++){
    float m = ps[sub*65 + d];
    a1 = fmaf(Wa_[o*65 + d], m, a1);
    a2 = fmaf(Wb_[o*65 + d], m, a2);
  }
  g_Z1s[row*128 + o]      = da * leaky_f(a1);
  g_Z1s[row*128 + 64 + o] = da * leaky_f(a2);
}

__device__ __forceinline__ void cos_role(int blk){
  int w = threadIdx.x >> 5;
  int lane = threadIdx.x & 31;
  int row = blk * 8 + w;
  ull t[4] = {0ull,0ull,0ull,0ull};
  if (lane < 16) t[0] = g_cand[row*16 + lane];
  #pragma unroll
  for (int off = 8; off >= 1; off >>= 1){
    ull r0 = __shfl_down_sync(0xffffffffu, t[0], off);
    ull r1 = __shfl_down_sync(0xffffffffu, t[1], off);
    ull r2 = __shfl_down_sync(0xffffffffu, t[2], off);
    ull r3 = __shfl_down_sync(0xffffffffu, t[3], off);
    top4_insert(t, r0); top4_insert(t, r1);
    top4_insert(t, r2); top4_insert(t, r3);
  }
  int idx[4];
  #pragma unroll
  for (int q = 0; q < 4; q++){
    ull k = __shfl_sync(0xffffffffu, t[q], 0);
    idx[q] = 2047 - (int)(unsigned int)(k & 0xFFFFFFFFull);
  }
  if (lane == 0){
    #pragma unroll
    for (int q = 0; q < 4; q++) g_idx[row*4 + q] = idx[q];
  }
  float c[4];
  #pragma unroll
  for (int q = 0; q < 4; q++){
    int j = idx[q];
    float s = g_hn[row*64 + lane]      * g_hn[j*64 + lane]
            + g_hn[row*64 + 32 + lane] * g_hn[j*64 + 32 + lane];
    for (int o = 16; o > 0; o >>= 1) s += __shfl_down_sync(0xffffffffu, s, o);
    c[q] = s;
  }
  if (lane == 0){
    float rs = c[0] + c[1] + c[2] + c[3];
    g_dc[row] = rsqrtf(rs + 1e-10f);
    #pragma unroll
    for (int q = 0; q < 4; q++) g_cval[row*4 + q] = c[q];
  }
}

// ============ 3. stage2: cos (256) || z1t (512) ============
__global__ __launch_bounds__(256) void k_stage2(const float* __restrict__ WT1, const float* __restrict__ bT1,
                                                const float* __restrict__ WC1, const float* __restrict__ bC1){
  __shared__ __align__(16) float smem[8580];
  int b = blockIdx.x;
  if (b < 256) cos_role(b);
  else z1t_role(b - 256, WT1, bT1, WC1, bC1, smem);
}

// z1f (R6 smem version)
__device__ __forceinline__ void z1f_role(int row4, const float* __restrict__ WF1, const float* __restrict__ bF1,
                                         const float* __restrict__ WC1, const float* __restrict__ bC1, float* smem){
  float* Wa_ = smem;
  float* Wb_ = smem + 4160;
  float* ms  = smem + 8320;   // 4x65
  int tid = threadIdx.x; int sub = tid >> 6; int o = tid & 63;
  for (int e = tid; e < 4096; e += 256){
    Wa_[(e>>6)*65 + (e&63)] = WF1[e];
    Wb_[(e>>6)*65 + (e&63)] = WC1[e];
  }
  int row = row4*4 + sub;
  float dci = g_dc[row];
  float m = 0.f;
  #pragma unroll
  for (int t = 0; t < 4; t++){
    int j = g_idx[row*4 + t];
    float coef = g_cval[row*4 + t] * dci * g_dc[j];
    m = fmaf(coef, g_h[j*64 + o], m);
  }
  ms[sub*65 + o] = m;
  __syncthreads();
  float a1 = bF1[o], a2 = bC1[o];
  #pragma unroll 16
  for (int d = 0; d < 64; d++){
    float v = ms[sub*65 + d];
    a1 = fmaf(Wa_[o*65 + d], v, a1);
    a2 = fmaf(Wb_[o*65 + d], v, a2);
  }
  g_Z1f[row*128 + o]      = leaky_f(a1);
  g_Z1f[row*128 + 64 + o] = leaky_f(a2);
}

// ============ 4. stage3: gemmA<128> (256) || z1f (512) ============
__global__ __launch_bounds__(256) void k_stage3(const float* __restrict__ A,
                                                const float* __restrict__ WF1, const float* __restrict__ bF1,
                                                const float* __restrict__ WC1, const float* __restrict__ bC1){
  __shared__ __align__(16) float smem[8608];
  int b = blockIdx.x;
  if (b < 256) gemm_role<128>(A, g_Z1s, b & 31, b >> 5, smem);
  else z1f_role(b - 256, WF1, bF1, WC1, bC1, smem);
}

__device__ __forceinline__ void z2t_role(int row4, const float* __restrict__ WT2, const float* __restrict__ bT2,
                                         const float* __restrict__ WC2, const float* __restrict__ bC2, float* smem){
  float* Wa_ = smem;
  float* Wb_ = smem + 4160;
  float* ps  = smem + 8320;   // 4x130
  float* red = smem + 8840;   // 4x64
  int tid = threadIdx.x; int sub = tid >> 6; int o = tid & 63;
  for (int e = tid; e < 4096; e += 256){
    Wa_[(e>>6)*65 + (e&63)] = WT2[e];
    Wb_[(e>>6)*65 + (e&63)] = WC2[e];
  }
  int row = row4*4 + sub;
  float da = g_dA[row];
  float pA = 0.f, pB = 0.f;
  #pragma unroll
  for (int s = 0; s < 8; s++){
    pA += g_part[(size_t)s*N*128 + row*128 + o];
    pB += g_part[(size_t)s*N*128 + row*128 + 64 + o];
  }
  ps[sub*130 + o]      = da * pA;
  ps[sub*130 + 64 + o] = da * pB;
  __syncthreads();
  float a1 = bT2[o], a2 = bC2[o];
  #pragma unroll 16
  for (int d = 0; d < 64; d++){
    a1 = fmaf(Wa_[o*65 + d], ps[sub*130 + d],      a1);
    a2 = fmaf(Wb_[o*65 + d], ps[sub*130 + 64 + d], a2);
  }
  float zt  = leaky_f(a1);
  float zct = leaky_f(a2);
  g_zt [row*64 + o] = zt;
  g_zct[row*64 + o] = zct;
  red[sub*64 + o] = zct*zct;
  __syncthreads();
  for (int off = 32; off > 0; off >>= 1){
    if (o < off) red[sub*64 + o] += red[sub*64 + o + off];
    __syncthreads();
  }
  float mn = sqrtf(red[sub*64] * 0.015625f) + 1e-10f;
  g_Lct[row*64 + o] = zct / mn;
}

__device__ __forceinline__ void z2f_role(int row4, const float* __restrict__ WF2, const float* __restrict__ bF2,
                                         const float* __restrict__ WC2, const float* __restrict__ bC2, float* smem){
  float* Wa_ = smem;
  float* Wb_ = smem + 4160;
  float* ms  = smem + 8320;   // 4x130
  float* red = smem + 8840;   // 4x64
  int tid = threadIdx.x; int sub = tid >> 6; int o = tid & 63;
  for (int e = tid; e < 4096; e += 256){
    Wa_[(e>>6)*65 + (e&63)] = WF2[e];
    Wb_[(e>>6)*65 + (e&63)] = WC2[e];
  }
  int row = row4*4 + sub;
  float dci = g_dc[row];
  float mf = 0.f, mc = 0.f;
  #pragma unroll
  for (int t = 0; t < 4; t++){
    int j = g_idx[row*4 + t];
    float coef = g_cval[row*4 + t] * dci * g_dc[j];
    mf = fmaf(coef, g_Z1f[j*128 + o],      mf);
    mc = fmaf(coef, g_Z1f[j*128 + 64 + o], mc);
  }
  ms[sub*130 + o]      = mf;
  ms[sub*130 + 64 + o] = mc;
  __syncthreads();
  float a1 = bF2[o], a2 = bC2[o];
  #pragma unroll 16
  for (int d = 0; d < 64; d++){
    a1 = fmaf(Wa_[o*65 + d], ms[sub*130 + d],      a1);
    a2 = fmaf(Wb_[o*65 + d], ms[sub*130 + 64 + d], a2);
  }
  float zf  = leaky_f(a1);
  float zcf = leaky_f(a2);
  g_zf [row*64 + o] = zf;
  g_zcf[row*64 + o] = zcf;
  red[sub*64 + o] = zcf*zcf;
  __syncthreads();
  for (int off = 32; off > 0; off >>= 1){
    if (o < off) red[sub*64 + o] += red[sub*64 + o + off];
    __syncthreads();
  }
  float mn = sqrtf(red[sub*64] * 0.015625f) + 1e-10f;
  g_Lcf[row*64 + o] = zcf / mn;
}

// ============ 5. stage4: z2t (512) || z2f (512) ============
__global__ __launch_bounds__(256) void k_stage4(const float* __restrict__ WT2, const float* __restrict__ bT2,
                                                const float* __restrict__ WF2, const float* __restrict__ bF2,
                                                const float* __restrict__ WC2, const float* __restrict__ bC2){
  __shared__ __align__(16) float smem[9096];
  int b = blockIdx.x;
  if (b < 512) z2t_role(b, WT2, bT2, WC2, bC2, smem);
  else z2f_role(b - 512, WF2, bF2, WC2, bC2, smem);
}

// ============ gram role ============
__device__ __forceinline__ void gram_role(int mode, int bx, int by, float* smem){
  float* As = smem;            // 64x17
  float* Bs = smem + 1088;     // 64x17
  float* mean = smem + 2176;   // 16
  const float *A0, *A1, *B0, *B1; double* out; int cb; int use_mean;
  if (mode == 0){ A0 = g_Lcf; A1 = g_Lct; B0 = g_Lcf; B1 = g_Lct; use_mean = 0; out = g_G; cb = 128; }
  else if (mode == 1){ A0 = g_zt; A1 = 0; B0 = g_zct; B1 = 0; use_mean = 1; out = g_M1; cb = 64; }
  else              { A0 = g_zf; A1 = 0; B0 = g_zcf; B1 = 0; use_mean = 1; out = g_M2; cb = 64; }
  int ci0 = bx * 16, cj0 = by * 16;
  const float* Ap = (ci0 < 64) ? A0 : A1; int ca_off = ci0 & 63;
  const float* Bp = (cj0 < 64) ? B0 : B1; int cb_off = cj0 & 63;
  int tid = threadIdx.x;
  int ty = tid >> 4, tx = tid & 15;
  if (use_mean){
    float s = 0.f;
    for (int r = ty; r < N; r += 16) s += Ap[r*64 + ca_off + tx];
    As[ty*17 + tx] = s;
    __syncthreads();
    if (ty == 0){
      float m = 0.f;
      #pragma unroll
      for (int k = 0; k < 16; k++) m += As[k*17 + tx];
      mean[tx] = m / (float)N;
    }
    __syncthreads();
  }
  double acc = 0.0; float f = 0.f;
  for (int n0 = 0; n0 < N; n0 += 64){
    __syncthreads();
    #pragma unroll
    for (int e = tid; e < 1024; e += 256){
      int r = n0 + (e >> 4);
      float av = Ap[r*64 + ca_off + (e & 15)];
      if (use_mean) av -= mean[e & 15];
      As[(e >> 4)*17 + (e & 15)] = av;
      Bs[(e >> 4)*17 + (e & 15)] = Bp[r*64 + cb_off + (e & 15)];
    }
    __syncthreads();
    #pragma unroll 16
    for (int r2 = 0; r2 < 64; r2++) f = fmaf(As[r2*17 + ty], Bs[r2*17 + tx], f);
    if (((n0 >> 6) & 1) == 1){ acc += (double)f; f = 0.f; }
  }
  out[(ci0 + ty)*cb + cj0 + tx] = acc;
}

__device__ __forceinline__ void att_role(int blk, const float* __restrict__ Wa, const float* __restrict__ ba,
                                         const float* __restrict__ q,  const float* __restrict__ W2,
                                         const float* __restrict__ b2, float* __restrict__ out, float* smem){
  float* Was = smem;            // 64x65
  float* qv  = smem + 4160;     // 64
  float* zsh = smem + 4224;     // 4x3x64
  float* red = smem + 4992;     // 4x64
  float* sv  = smem + 5248;     // 4x3
  float* av  = smem + 5260;     // 4x3
  float* zag = smem + 5272;     // 4x64
  int tid = threadIdx.x; int sub = tid >> 6; int o = tid & 63;
  for (int e = tid; e < 4096; e += 256) Was[(e>>6)*65 + (e&63)] = Wa[e];
  if (tid < 64) qv[tid] = q[tid];
  __syncthreads();
  int row = blk*4 + sub;
  float zfv  = g_zf [row*64 + o];
  float ztv  = g_zt [row*64 + o];
  float zcv  = 0.5f*(g_zcf[row*64 + o] + g_zct[row*64 + o]);
  zsh[(sub*3 + 0)*64 + o] = zfv;
  zsh[(sub*3 + 1)*64 + o] = ztv;
  zsh[(sub*3 + 2)*64 + o] = zcv;
  __syncthreads();
  #pragma unroll
  for (int kk = 0; kk < 3; kk++){
    float t = ba[o];
    #pragma unroll 16
    for (int d = 0; d < 64; d++) t = fmaf(Was[o*65 + d], zsh[(sub*3 + kk)*64 + d], t);
    t = tanhf(t) * qv[o];
    red[sub*64 + o] = t;
    __syncthreads();
    if (o < 32) red[sub*64 + o] += red[sub*64 + o + 32];
    __syncthreads();
    if (o < 32){
      float s = red[sub*64 + o];
      for (int off = 16; off > 0; off >>= 1) s += __shfl_down_sync(0xffffffffu, s, off);
      if (o == 0) sv[sub*3 + kk] = s;
    }
    __syncthreads();
  }
  if (o == 0){
    float m = fmaxf(sv[sub*3], fmaxf(sv[sub*3+1], sv[sub*3+2]));
    float e0 = expf(sv[sub*3]-m), e1 = expf(sv[sub*3+1]-m), e2 = expf(sv[sub*3+2]-m);
    float inv = 1.f/(e0+e1+e2);
    av[sub*3] = e0*inv; av[sub*3+1] = e1*inv; av[sub*3+2] = e2*inv;
  }
  __syncthreads();
  zag[sub*64 + o] = av[sub*3]*zfv + av[sub*3+1]*ztv + av[sub*3+2]*zcv;
  __syncthreads();
  if (o < 7){
    float v = b2[o];
    #pragma unroll 16
    for (int d = 0; d < 64; d++) v = fmaf(W2[o*64 + d], zag[sub*64 + d], v);
    out[row*7 + o] = v;
  }
}

// ============ 6. stage5: gram x3 (96) || att (512), fused final via ticket ============
__global__ __launch_bounds__(256) void k_stage5(const float* __restrict__ Wa, const float* __restrict__ ba,
                                                const float* __restrict__ q,  const float* __restrict__ W2,
                                                const float* __restrict__ b2, float* __restrict__ out){
  __shared__ __align__(16) float smem[5536];
  __shared__ unsigned int s_last;
  int b = blockIdx.x;
  int tid = threadIdx.x;
  if (b < 96){
    if (b < 64)      gram_role(0, b >> 3, b & 7, smem);
    else if (b < 80) gram_role(1, (b - 64) >> 2, (b - 64) & 3, smem);
    else             gram_role(2, (b - 80) >> 2, (b - 80) & 3, smem);
    __threadfence();
    __syncthreads();
    if (tid == 0) s_last = (atomicAdd(&g_ticket, 1u) == 95u) ? 1u : 0u;
    __syncthreads();
    if (s_last){
      if (tid == 0) g_ticket = 0u;
      __threadfence();
      double lc = 0.0, ld = 0.0;
      for (int e = tid; e < 128*128; e += 256){
        int a = e >> 7, bb = e & 127;
        double s = ((a < 64) == (bb < 64)) ? 1.0 : -1.0;
        double g = g_G[e];
        lc += s * g * g;
      }
      for (int e = tid; e < 64*64; e += 256){
        double m1 = g_M1[e]; ld += m1*m1;
        double m2 = g_M2[e]; ld += m2*m2;
      }
      double* s1 = (double*)smem;
      double* s2 = s1 + 256;
      s1[tid] = lc; s2[tid] = ld; __syncthreads();
      for (int o = 128; o > 0; o >>= 1){
        if (tid < o){ s1[tid] += s1[tid + o]; s2[tid] += s2[tid + o]; }
        __syncthreads();
      }
      if (tid == 0){
        out[N*7]     = (float)(s1[0] / ((double)N * (double)N));
        out[N*7 + 1] = (float)(s2[0] / (2047.0 * 2047.0));
      }
    }
  } else {
    att_role(b - 96, Wa, ba, q, W2, b2, out, smem);
  }
}

extern "C" void kernel_launch(void* const* d_in, const int* in_sizes, int n_in,
                              void* d_out, int out_size){
  const float* x   = (const float*)d_in[0];
  const float* A   = (const float*)d_in[1];
  const float* W1  = (const float*)d_in[3];
  const float* b1  = (const float*)d_in[4];
  const float* WF1 = (const float*)d_in[5];
  const float* bF1 = (const float*)d_in[6];
  const float* WF2 = (const float*)d_in[7];
  const float* bF2 = (const float*)d_in[8];
  const float* WT1 = (const float*)d_in[9];
  const float* bT1 = (const float*)d_in[10];
  const float* WT2 = (const float*)d_in[11];
  const float* bT2 = (const float*)d_in[12];
  const float* WC1 = (const float*)d_in[13];
  const float* bC1 = (const float*)d_in[14];
  const float* WC2 = (const float*)d_in[15];
  const float* bC2 = (const float*)d_in[16];
  const float* Wa  = (const float*)d_in[17];
  const float* ba  = (const float*)d_in[18];
  const float* q   = (const float*)d_in[19];
  const float* W2  = (const float*)d_in[20];
  const float* b2  = (const float*)d_in[21];
  float* out = (float*)d_out;

  k_pre   <<<N/16, 256>>>(A, x, W1, b1);
  k_stage1<<<512,  256>>>(A);
  k_stage2<<<768,  256>>>(WT1, bT1, WC1, bC1);
  k_stage3<<<768,  256>>>(A, WF1, bF1, WC1, bC1);
  k_stage4<<<1024, 256>>>(WT2, bT2, WF2, bF2, WC2, bC2);
  k_stage5<<<608,  256>>>(Wa, ba, q, W2, b2, out);
}

// round 11
// speedup vs baseline: 1.0944x; 1.0320x over previous
#include <cuda_runtime.h>
#include <math.h>
#include <stdint.h>

#define N 2048
#define H 64

typedef unsigned long long ull;

__device__ float g_dA[N];
__device__ float g_h[N*H];
__device__ float g_hn[N*H];
__device__ float g_hd[N*H];
__device__ float g_hsq[N];
__device__ ull   g_cand[N*32];
__device__ int   g_idx[N*4];
__device__ float g_cval[N*4];
__device__ float g_dc[N];
__device__ float g_Z1s[N*2*H];
__device__ float g_Z1f[N*2*H];
__device__ float g_part[16*N*2*H];
__device__ float g_zf[N*H], g_zt[N*H], g_zcf[N*H], g_zct[N*H];
__device__ float g_Lcf[N*H], g_Lct[N*H];
__device__ double g_G[128*128];
__device__ double g_M1[64*64];
__device__ double g_M2[64*64];
__device__ unsigned int g_ticket;

__device__ __forceinline__ float leaky_f(float v){ return v > 0.f ? v : 0.1f*v; }

__device__ __forceinline__ unsigned int fmap(float v){
  unsigned int u = __float_as_uint(v);
  return (u & 0x80000000u) ? ~u : (u | 0x80000000u);
}

__device__ __forceinline__ void top4_insert(ull* t, ull key){
  if (key > t[3]) {
    t[3] = key;
    ull tmp;
    if (t[3] > t[2]) { tmp = t[2]; t[2] = t[3]; t[3] = tmp; }
    if (t[2] > t[1]) { tmp = t[1]; t[1] = t[2]; t[2] = tmp; }
    if (t[1] > t[0]) { tmp = t[0]; t[0] = t[1]; t[1] = tmp; }
  }
}

__device__ __forceinline__ ull pk2(float lo, float hi){
  ull r;
  asm("mov.b64 %0, {%1, %2};" : "=l"(r) : "f"(lo), "f"(hi));
  return r;
}
__device__ __forceinline__ void upk2(ull v, float& lo, float& hi){
  asm("mov.b64 {%0, %1}, %2;" : "=f"(lo), "=f"(hi) : "l"(v));
}
__device__ __forceinline__ ull ffma2(ull a, ull b, ull c){
  ull r;
  asm("fma.rn.f32x2 %0, %1, %2, %3;" : "=l"(r) : "l"(a), "l"(b), "l"(c));
  return r;
}

// ============ 1. fused: rowsum(A) + h + hn/hd/hsq ============
__global__ __launch_bounds__(256) void k_pre(const float* __restrict__ A,
                                             const float* __restrict__ x,
                                             const float* __restrict__ W1,
                                             const float* __restrict__ b1){
  __shared__ float Ws[64][129];
  __shared__ float xs[16][128];
  __shared__ float hs[16][65];
  __shared__ float ss[16];
  __shared__ float das[16];
  int tid = threadIdx.x;
  int base = blockIdx.x * 16;
  for (int e = tid; e < 64*128; e += 256) Ws[e>>7][e&127] = W1[e];
  for (int e = tid; e < 16*128; e += 256) xs[e>>7][e&127] = x[(size_t)base*128 + e];
  {
    int w = tid >> 5, lane = tid & 31;
    int r0 = base + w*2;
    const float* p0 = A + (size_t)r0*N;
    const float* p1 = p0 + N;
    float s0 = 0.f, s1 = 0.f;
    for (int i = lane; i < N; i += 32){ s0 += p0[i]; s1 += p1[i]; }
    for (int o = 16; o > 0; o >>= 1){
      s0 += __shfl_down_sync(0xffffffffu, s0, o);
      s1 += __shfl_down_sync(0xffffffffu, s1, o);
    }
    if (lane == 0){
      float d0 = rsqrtf(s0 + 1e-10f), d1 = rsqrtf(s1 + 1e-10f);
      das[w*2] = d0; das[w*2+1] = d1;
      g_dA[r0] = d0; g_dA[r0+1] = d1;
    }
  }
  __syncthreads();
  int o = tid & 63, rg = tid >> 6;
  float hv[4];
  #pragma unroll
  for (int rr = 0; rr < 4; rr++){
    int rl = rg*4 + rr;
    float a = b1[o];
    #pragma unroll 16
    for (int d = 0; d < 128; d++) a = fmaf(Ws[o][d], xs[rl][d], a);
    hv[rr] = leaky_f(a);
    hs[rl][o] = hv[rr];
  }
  __syncthreads();
  if (tid < 16){
    float s = 0.f;
    #pragma unroll 8
    for (int d = 0; d < 64; d++) s = fmaf(hs[tid][d], hs[tid][d], s);
    ss[tid] = s;
    g_hsq[base + tid] = s;
  }
  __syncthreads();
  #pragma unroll
  for (int rr = 0; rr < 4; rr++){
    int rl = rg*4 + rr, row = base + rl;
    float rn = rsqrtf(ss[rl]);
    float v = hv[rr];
    g_h [row*64 + o] = v;
    g_hn[row*64 + o] = v*rn + 1e-10f;
    g_hd[row*64 + o] = v*das[rl];
  }
}

// ============ split-K GEMM over A: 16 ksplits, double-buffered ============
template<int C>
__device__ __forceinline__ void gemm_role(const float* __restrict__ A,
                                          const float* __restrict__ B,
                                          int rowblk, int ksplit, float* smem){
  constexpr int CPT = C / 16;
  constexpr int BPT = C / 16;
  float* Asb[2] = {smem, smem + 1088};                    // [16][68]
  float* Bsb[2] = {smem + 2176, smem + 2176 + 16*(C+4)};  // [16][C+4]
  int tid = threadIdx.x;
  int rowbase = rowblk * 64;
  int kb0 = ksplit * 128;
  int r0 = (tid >> 4) * 4, c0 = (tid & 15) * CPT;
  ull acc[4][CPT/2];
  #pragma unroll
  for (int i = 0; i < 4; i++)
    #pragma unroll
    for (int j = 0; j < CPT/2; j++) acc[i][j] = 0ull;
  float ra[4], rb[BPT];
  #pragma unroll
  for (int i = 0; i < 4; i++){
    int e = tid + i*256;
    ra[i] = A[(size_t)(rowbase + (e>>4))*N + kb0 + (e&15)];
  }
  #pragma unroll
  for (int i = 0; i < BPT; i++){
    int e = tid + i*256;
    rb[i] = B[(kb0 + e/C)*C + (e%C)];
  }
  #pragma unroll
  for (int i = 0; i < 4; i++){
    int e = tid + i*256;
    Asb[0][(e&15)*68 + (e>>4)] = ra[i];
  }
  #pragma unroll
  for (int i = 0; i < BPT; i++){
    int e = tid + i*256;
    Bsb[0][(e/C)*(C+4) + (e%C)] = rb[i];
  }
  __syncthreads();
  for (int t = 0; t < 8; t++){
    int cur = t & 1;
    if (t < 7){
      int kn = kb0 + (t+1)*16;
      #pragma unroll
      for (int i = 0; i < 4; i++){
        int e = tid + i*256;
        ra[i] = A[(size_t)(rowbase + (e>>4))*N + kn + (e&15)];
      }
      #pragma unroll
      for (int i = 0; i < BPT; i++){
        int e = tid + i*256;
        rb[i] = B[(kn + e/C)*C + (e%C)];
      }
    }
    const float* As = Asb[cur];
    const float* Bs = Bsb[cur];
    #pragma unroll
    for (int kk = 0; kk < 16; kk++){
      float4 a4 = *(const float4*)&As[kk*68 + r0];
      ull a[4] = {pk2(a4.x,a4.x), pk2(a4.y,a4.y), pk2(a4.z,a4.z), pk2(a4.w,a4.w)};
      #pragma unroll
      for (int j4 = 0; j4 < CPT/4; j4++){
        ulonglong2 bv = *(const ulonglong2*)&Bs[kk*(C+4) + c0 + j4*4];
        #pragma unroll
        for (int i = 0; i < 4; i++){
          acc[i][j4*2]   = ffma2(a[i], bv.x, acc[i][j4*2]);
          acc[i][j4*2+1] = ffma2(a[i], bv.y, acc[i][j4*2+1]);
        }
      }
    }
    if (t < 7){
      int nxt = 1 - cur;
      #pragma unroll
      for (int i = 0; i < 4; i++){
        int e = tid + i*256;
        Asb[nxt][(e&15)*68 + (e>>4)] = ra[i];
      }
      #pragma unroll
      for (int i = 0; i < BPT; i++){
        int e = tid + i*256;
        Bsb[nxt][(e/C)*(C+4) + (e%C)] = rb[i];
      }
    }
    __syncthreads();
  }
  float* dst = g_part + (size_t)ksplit * N * C;
  #pragma unroll
  for (int i = 0; i < 4; i++)
    #pragma unroll
    for (int j = 0; j < CPT/2; j++){
      float lo, hi;
      upk2(acc[i][j], lo, hi);
      dst[(rowbase + r0 + i)*C + c0 + 2*j]     = lo;
      dst[(rowbase + r0 + i)*C + c0 + 2*j + 1] = hi;
    }
}

// ============ 2. stage1: heat-top4 (512, jsplit 8) || gemmA<64> (512) ============
__global__ __launch_bounds__(256) void k_stage1(const float* __restrict__ A){
  __shared__ __align__(16) float smem[11040];
  int b = blockIdx.x, tid = threadIdx.x;
  if (b < 512){
    float* As   = smem;                           // [64 d][34 r]
    float* Bsb[2] = {smem + 2176, smem + 6528};   // [64 d][68 j]
    float* asq  = smem + 10880;
    float* bqb[2] = {smem + 10912, smem + 10976};
    int rowbase = (b & 63) * 32;
    int jsplit  = b >> 6;          // 0..7
    int jbase   = jsplit * 256;
    int r0 = (tid >> 4) * 2, c0 = (tid & 15) * 4;
    #pragma unroll
    for (int i = 0; i < 8; i++){
      int e = tid + i*256;
      As[(e & 63)*34 + (e >> 6)] = g_h[(rowbase + (e >> 6))*64 + (e & 63)];
    }
    if (tid < 32) asq[tid] = g_hsq[rowbase + tid];
    float rb[16], rq;
    #pragma unroll
    for (int i = 0; i < 16; i++){
      int e = tid + i*256;
      rb[i] = g_h[(jbase + (e >> 6))*64 + (e & 63)];
    }
    rq = (tid < 64) ? g_hsq[jbase + tid] : 0.f;
    #pragma unroll
    for (int i = 0; i < 16; i++){
      int e = tid + i*256;
      Bsb[0][(e & 63)*68 + (e >> 6)] = rb[i];
    }
    if (tid < 64) bqb[0][tid] = rq;
    __syncthreads();
    float asqr0 = asq[r0], asqr1 = asq[r0+1];
    ull t[2][4];
    #pragma unroll
    for (int i = 0; i < 2; i++)
      #pragma unroll
      for (int q = 0; q < 4; q++) t[i][q] = 0ull;
    for (int tile = 0; tile < 4; tile++){
      int cur = tile & 1;
      int jc = jbase + tile*64;
      if (tile < 3){
        int jn = jc + 64;
        #pragma unroll
        for (int i = 0; i < 16; i++){
          int e = tid + i*256;
          rb[i] = g_h[(jn + (e >> 6))*64 + (e & 63)];
        }
        rq = (tid < 64) ? g_hsq[jn + tid] : 0.f;
      }
      const float* Bs = Bsb[cur];
      const float* bsq = bqb[cur];
      ull acc[2][2] = {{0ull,0ull},{0ull,0ull}};
      #pragma unroll 8
      for (int kk = 0; kk < 64; kk++){
        float2 a2 = *(const float2*)&As[kk*34 + r0];
        ull avx = pk2(a2.x, a2.x);
        ull avy = pk2(a2.y, a2.y);
        ulonglong2 bv = *(const ulonglong2*)&Bs[kk*68 + c0];
        acc[0][0] = ffma2(avx, bv.x, acc[0][0]);
        acc[0][1] = ffma2(avx, bv.y, acc[0][1]);
        acc[1][0] = ffma2(avy, bv.x, acc[1][0]);
        acc[1][1] = ffma2(avy, bv.y, acc[1][1]);
      }
      float bq[4] = {bsq[c0], bsq[c0+1], bsq[c0+2], bsq[c0+3]};
      #pragma unroll
      for (int i = 0; i < 2; i++){
        float asqr = i ? asqr1 : asqr0;
        float d0, d1, d2, d3;
        upk2(acc[i][0], d0, d1);
        upk2(acc[i][1], d2, d3);
        float dd[4] = {d0, d1, d2, d3};
        #pragma unroll
        for (int j = 0; j < 4; j++){
          float dist = asqr + bq[j] - 2.f*dd[j] + 6.4e-9f;
          int jg = jc + c0 + j;
          ull key = ((ull)fmap(-dist) << 32) | (unsigned int)(2047 - jg);
          top4_insert(t[i], key);
        }
      }
      if (tile < 3){
        int nxt = 1 - cur;
        #pragma unroll
        for (int i = 0; i < 16; i++){
          int e = tid + i*256;
          Bsb[nxt][(e & 63)*68 + (e >> 6)] = rb[i];
        }
        if (tid < 64) bqb[nxt][tid] = rq;
      }
      __syncthreads();
    }
    ull* cand = (ull*)smem;
    __syncthreads();
    #pragma unroll
    for (int i = 0; i < 2; i++)
      #pragma unroll
      for (int q = 0; q < 4; q++)
        cand[(r0 + i)*64 + c0 + q] = t[i][q];
    __syncthreads();
    if (tid < 32){
      ull m[4] = {0ull,0ull,0ull,0ull};
      for (int e = 0; e < 64; e++) top4_insert(m, cand[tid*64 + e]);
      #pragma unroll
      for (int q = 0; q < 4; q++)
        g_cand[(rowbase + tid)*32 + jsplit*4 + q] = m[q];
    }
  } else {
    int bb = b - 512;
    gemm_role<64>(A, g_hd, bb & 31, bb >> 5, smem);
  }
}

// ============ z-layer roles (batched rows) ============
__device__ __forceinline__ void z1t_role(int rb, const float* __restrict__ WT1, const float* __restrict__ bT1,
                                         const float* __restrict__ WC1, const float* __restrict__ bC1, float* smem){
  float* Wa_ = smem;            // 64x65
  float* Wb_ = smem + 4160;     // 64x65
  float* ps  = smem + 8320;     // 32x65
  int tid = threadIdx.x; int sub = tid >> 6; int o = tid & 63;
  for (int e = tid; e < 4096; e += 256){
    Wa_[(e>>6)*65 + (e&63)] = WT1[e];
    Wb_[(e>>6)*65 + (e&63)] = WC1[e];
  }
  int base = rb*32 + sub*8;
  float das[8];
  #pragma unroll
  for (int r = 0; r < 8; r++){
    int row = base + r;
    float p = 0.f;
    #pragma unroll
    for (int s = 0; s < 16; s++) p += g_part[(size_t)s*N*64 + row*64 + o];
    das[r] = g_dA[row];
    ps[(sub*8 + r)*65 + o] = das[r] * p;
  }
  __syncthreads();
  float b1v = bT1[o], b2v = bC1[o];
  float a1[8], a2[8];
  #pragma unroll
  for (int r = 0; r < 8; r++){ a1[r] = b1v; a2[r] = b2v; }
  #pragma unroll 8
  for (int d = 0; d < 64; d++){
    float wa = Wa_[o*65 + d], wb = Wb_[o*65 + d];
    #pragma unroll
    for (int r = 0; r < 8; r++){
      float m = ps[(sub*8 + r)*65 + d];
      a1[r] = fmaf(wa, m, a1[r]);
      a2[r] = fmaf(wb, m, a2[r]);
    }
  }
  #pragma unroll
  for (int r = 0; r < 8; r++){
    int row = base + r;
    g_Z1s[row*128 + o]      = das[r] * leaky_f(a1[r]);
    g_Z1s[row*128 + 64 + o] = das[r] * leaky_f(a2[r]);
  }
}

__device__ __forceinline__ void cos_role(int blk){
  int w = threadIdx.x >> 5;
  int lane = threadIdx.x & 31;
  int row = blk * 8 + w;
  ull t[4] = {0ull,0ull,0ull,0ull};
  t[0] = g_cand[row*32 + lane];
  #pragma unroll
  for (int off = 16; off >= 1; off >>= 1){
    ull r0 = __shfl_down_sync(0xffffffffu, t[0], off);
    ull r1 = __shfl_down_sync(0xffffffffu, t[1], off);
    ull r2 = __shfl_down_sync(0xffffffffu, t[2], off);
    ull r3 = __shfl_down_sync(0xffffffffu, t[3], off);
    top4_insert(t, r0); top4_insert(t, r1);
    top4_insert(t, r2); top4_insert(t, r3);
  }
  int idx[4];
  #pragma unroll
  for (int q = 0; q < 4; q++){
    ull k = __shfl_sync(0xffffffffu, t[q], 0);
    idx[q] = 2047 - (int)(unsigned int)(k & 0xFFFFFFFFull);
  }
  if (lane == 0){
    #pragma unroll
    for (int q = 0; q < 4; q++) g_idx[row*4 + q] = idx[q];
  }
  float c[4];
  #pragma unroll
  for (int q = 0; q < 4; q++){
    int j = idx[q];
    float s = g_hn[row*64 + lane]      * g_hn[j*64 + lane]
            + g_hn[row*64 + 32 + lane] * g_hn[j*64 + 32 + lane];
    for (int o = 16; o > 0; o >>= 1) s += __shfl_down_sync(0xffffffffu, s, o);
    c[q] = s;
  }
  if (lane == 0){
    float rs = c[0] + c[1] + c[2] + c[3];
    g_dc[row] = rsqrtf(rs + 1e-10f);
    #pragma unroll
    for (int q = 0; q < 4; q++) g_cval[row*4 + q] = c[q];
  }
}

// ============ 3. stage2: cos (256) || z1t (64) ============
__global__ __launch_bounds__(256) void k_stage2(const float* __restrict__ WT1, const float* __restrict__ bT1,
                                                const float* __restrict__ WC1, const float* __restrict__ bC1){
  __shared__ __align__(16) float smem[10400];
  int b = blockIdx.x;
  if (b < 256) cos_role(b);
  else z1t_role(b - 256, WT1, bT1, WC1, bC1, smem);
}

__device__ __forceinline__ void z1f_role(int rb, const float* __restrict__ WF1, const float* __restrict__ bF1,
                                         const float* __restrict__ WC1, const float* __restrict__ bC1, float* smem){
  float* Wa_ = smem;
  float* Wb_ = smem + 4160;
  float* ps  = smem + 8320;   // 32x65
  int tid = threadIdx.x; int sub = tid >> 6; int o = tid & 63;
  for (int e = tid; e < 4096; e += 256){
    Wa_[(e>>6)*65 + (e&63)] = WF1[e];
    Wb_[(e>>6)*65 + (e&63)] = WC1[e];
  }
  int base = rb*32 + sub*8;
  #pragma unroll
  for (int r = 0; r < 8; r++){
    int row = base + r;
    float dci = g_dc[row];
    float m = 0.f;
    #pragma unroll
    for (int t = 0; t < 4; t++){
      int j = g_idx[row*4 + t];
      float coef = g_cval[row*4 + t] * dci * g_dc[j];
      m = fmaf(coef, g_h[j*64 + o], m);
    }
    ps[(sub*8 + r)*65 + o] = m;
  }
  __syncthreads();
  float b1v = bF1[o], b2v = bC1[o];
  float a1[8], a2[8];
  #pragma unroll
  for (int r = 0; r < 8; r++){ a1[r] = b1v; a2[r] = b2v; }
  #pragma unroll 8
  for (int d = 0; d < 64; d++){
    float wa = Wa_[o*65 + d], wb = Wb_[o*65 + d];
    #pragma unroll
    for (int r = 0; r < 8; r++){
      float m = ps[(sub*8 + r)*65 + d];
      a1[r] = fmaf(wa, m, a1[r]);
      a2[r] = fmaf(wb, m, a2[r]);
    }
  }
  #pragma unroll
  for (int r = 0; r < 8; r++){
    int row = base + r;
    g_Z1f[row*128 + o]      = leaky_f(a1[r]);
    g_Z1f[row*128 + 64 + o] = leaky_f(a2[r]);
  }
}

// ============ 4. stage3: gemmA<128> (512) || z1f (64) ============
__global__ __launch_bounds__(256) void k_stage3(const float* __restrict__ A,
                                                const float* __restrict__ WF1, const float* __restrict__ bF1,
                                                const float* __restrict__ WC1, const float* __restrict__ bC1){
  __shared__ __align__(16) float smem[10400];
  int b = blockIdx.x;
  if (b < 512) gemm_role<128>(A, g_Z1s, b & 31, b >> 5, smem);
  else z1f_role(b - 512, WF1, bF1, WC1, bC1, smem);
}

__device__ __forceinline__ void z2t_role(int rb, const float* __restrict__ WT2, const float* __restrict__ bT2,
                                         const float* __restrict__ WC2, const float* __restrict__ bC2, float* smem){
  float* Wa_ = smem;
  float* Wb_ = smem + 4160;
  float* ps  = smem + 8320;   // 16x130
  float* red = smem + 10400;  // 4x64
  int tid = threadIdx.x; int sub = tid >> 6; int o = tid & 63;
  for (int e = tid; e < 4096; e += 256){
    Wa_[(e>>6)*65 + (e&63)] = WT2[e];
    Wb_[(e>>6)*65 + (e&63)] = WC2[e];
  }
  int base = rb*16 + sub*4;
  float das[4];
  #pragma unroll
  for (int r = 0; r < 4; r++){
    int row = base + r;
    float pA = 0.f, pB = 0.f;
    #pragma unroll
    for (int s = 0; s < 16; s++){
      pA += g_part[(size_t)s*N*128 + row*128 + o];
      pB += g_part[(size_t)s*N*128 + row*128 + 64 + o];
    }
    das[r] = g_dA[row];
    ps[(sub*4 + r)*130 + o]      = das[r] * pA;
    ps[(sub*4 + r)*130 + 64 + o] = das[r] * pB;
  }
  __syncthreads();
  float b1v = bT2[o], b2v = bC2[o];
  float a1[4], a2[4];
  #pragma unroll
  for (int r = 0; r < 4; r++){ a1[r] = b1v; a2[r] = b2v; }
  #pragma unroll 8
  for (int d = 0; d < 64; d++){
    float wa = Wa_[o*65 + d], wb = Wb_[o*65 + d];
    #pragma unroll
    for (int r = 0; r < 4; r++){
      a1[r] = fmaf(wa, ps[(sub*4 + r)*130 + d],      a1[r]);
      a2[r] = fmaf(wb, ps[(sub*4 + r)*130 + 64 + d], a2[r]);
    }
  }
  #pragma unroll
  for (int r = 0; r < 4; r++){
    int row = base + r;
    float zt  = leaky_f(a1[r]);
    float zct = leaky_f(a2[r]);
    g_zt [row*64 + o] = zt;
    g_zct[row*64 + o] = zct;
    __syncthreads();
    red[sub*64 + o] = zct*zct;
    __syncthreads();
    for (int off = 32; off > 0; off >>= 1){
      if (o < off) red[sub*64 + o] += red[sub*64 + o + off];
      __syncthreads();
    }
    float mn = sqrtf(red[sub*64] * 0.015625f) + 1e-10f;
    g_Lct[row*64 + o] = zct / mn;
  }
}

__device__ __forceinline__ void z2f_role(int rb, const float* __restrict__ WF2, const float* __restrict__ bF2,
                                         const float* __restrict__ WC2, const float* __restrict__ bC2, float* smem){
  float* Wa_ = smem;
  float* Wb_ = smem + 4160;
  float* ps  = smem + 8320;   // 16x130
  float* red = smem + 10400;  // 4x64
  int tid = threadIdx.x; int sub = tid >> 6; int o = tid & 63;
  for (int e = tid; e < 4096; e += 256){
    Wa_[(e>>6)*65 + (e&63)] = WF2[e];
    Wb_[(e>>6)*65 + (e&63)] = WC2[e];
  }
  int base = rb*16 + sub*4;
  #pragma unroll
  for (int r = 0; r < 4; r++){
    int row = base + r;
    float dci = g_dc[row];
    float mf = 0.f, mc = 0.f;
    #pragma unroll
    for (int t = 0; t < 4; t++){
      int j = g_idx[row*4 + t];
      float coef = g_cval[row*4 + t] * dci * g_dc[j];
      mf = fmaf(coef, g_Z1f[j*128 + o],      mf);
      mc = fmaf(coef, g_Z1f[j*128 + 64 + o], mc);
    }
    ps[(sub*4 + r)*130 + o]      = mf;
    ps[(sub*4 + r)*130 + 64 + o] = mc;
  }
  __syncthreads();
  float b1v = bF2[o], b2v = bC2[o];
  float a1[4], a2[4];
  #pragma unroll
  for (int r = 0; r < 4; r++){ a1[r] = b1v; a2[r] = b2v; }
  #pragma unroll 8
  for (int d = 0; d < 64; d++){
    float wa = Wa_[o*65 + d], wb = Wb_[o*65 + d];
    #pragma unroll
    for (int r = 0; r < 4; r++){
      a1[r] = fmaf(wa, ps[(sub*4 + r)*130 + d],      a1[r]);
      a2[r] = fmaf(wb, ps[(sub*4 + r)*130 + 64 + d], a2[r]);
    }
  }
  #pragma unroll
  for (int r = 0; r < 4; r++){
    int row = base + r;
    float zf  = leaky_f(a1[r]);
    float zcf = leaky_f(a2[r]);
    g_zf [row*64 + o] = zf;
    g_zcf[row*64 + o] = zcf;
    __syncthreads();
    red[sub*64 + o] = zcf*zcf;
    __syncthreads();
    for (int off = 32; off > 0; off >>= 1){
      if (o < off) red[sub*64 + o] += red[sub*64 + o + off];
      __syncthreads();
    }
    float mn = sqrtf(red[sub*64] * 0.015625f) + 1e-10f;
    g_Lcf[row*64 + o] = zcf / mn;
  }
}

// ============ 5. stage4: z2t (128) || z2f (128) ============
__global__ __launch_bounds__(256) void k_stage4(const float* __restrict__ WT2, const float* __restrict__ bT2,
                                                const float* __restrict__ WF2, const float* __restrict__ bF2,
                                                const float* __restrict__ WC2, const float* __restrict__ bC2){
  __shared__ __align__(16) float smem[10656];
  int b = blockIdx.x;
  if (b < 128) z2t_role(b, WT2, bT2, WC2, bC2, smem);
  else z2f_role(b - 128, WF2, bF2, WC2, bC2, smem);
}

// ============ gram role ============
__device__ __forceinline__ void gram_role(int mode, int bx, int by, float* smem){
  float* As = smem;            // 64x17
  float* Bs = smem + 1088;     // 64x17
  float* mean = smem + 2176;   // 16
  const float *A0, *A1, *B0, *B1; double* out; int cb; int use_mean;
  if (mode == 0){ A0 = g_Lcf; A1 = g_Lct; B0 = g_Lcf; B1 = g_Lct; use_mean = 0; out = g_G; cb = 128; }
  else if (mode == 1){ A0 = g_zt; A1 = 0; B0 = g_zct; B1 = 0; use_mean = 1; out = g_M1; cb = 64; }
  else              { A0 = g_zf; A1 = 0; B0 = g_zcf; B1 = 0; use_mean = 1; out = g_M2; cb = 64; }
  int ci0 = bx * 16, cj0 = by * 16;
  const float* Ap = (ci0 < 64) ? A0 : A1; int ca_off = ci0 & 63;
  const float* Bp = (cj0 < 64) ? B0 : B1; int cb_off = cj0 & 63;
  int tid = threadIdx.x;
  int ty = tid >> 4, tx = tid & 15;
  if (use_mean){
    float s = 0.f;
    for (int r = ty; r < N; r += 16) s += Ap[r*64 + ca_off + tx];
    As[ty*17 + tx] = s;
    __syncthreads();
    if (ty == 0){
      float m = 0.f;
      #pragma unroll
      for (int k = 0; k < 16; k++) m += As[k*17 + tx];
      mean[tx] = m / (float)N;
    }
    __syncthreads();
  }
  double acc = 0.0; float f = 0.f;
  for (int n0 = 0; n0 < N; n0 += 64){
    __syncthreads();
    #pragma unroll
    for (int e = tid; e < 1024; e += 256){
      int r = n0 + (e >> 4);
      float av = Ap[r*64 + ca_off + (e & 15)];
      if (use_mean) av -= mean[e & 15];
      As[(e >> 4)*17 + (e & 15)] = av;
      Bs[(e >> 4)*17 + (e & 15)] = Bp[r*64 + cb_off + (e & 15)];
    }
    __syncthreads();
    #pragma unroll 16
    for (int r2 = 0; r2 < 64; r2++) f = fmaf(As[r2*17 + ty], Bs[r2*17 + tx], f);
    if (((n0 >> 6) & 1) == 1){ acc += (double)f; f = 0.f; }
  }
  out[(ci0 + ty)*cb + cj0 + tx] = acc;
}

__device__ __forceinline__ void att_role(int blk, const float* __restrict__ Wa, const float* __restrict__ ba,
                                         const float* __restrict__ q,  const float* __restrict__ W2,
                                         const float* __restrict__ b2, float* __restrict__ out, float* smem){
  float* Was = smem;            // 64x65
  float* qv  = smem + 4160;     // 64
  float* zsh = smem + 4224;     // 4x3x64
  float* red = smem + 4992;     // 4x64
  float* sv  = smem + 5248;     // 4x3
  float* av  = smem + 5260;     // 4x3
  float* zag = smem + 5272;     // 4x64
  int tid = threadIdx.x; int sub = tid >> 6; int o = tid & 63;
  for (int e = tid; e < 4096; e += 256) Was[(e>>6)*65 + (e&63)] = Wa[e];
  if (tid < 64) qv[tid] = q[tid];
  __syncthreads();
  for (int r = 0; r < 4; r++){
    int row = blk*16 + sub*4 + r;
    float zfv  = g_zf [row*64 + o];
    float ztv  = g_zt [row*64 + o];
    float zcv  = 0.5f*(g_zcf[row*64 + o] + g_zct[row*64 + o]);
    zsh[(sub*3 + 0)*64 + o] = zfv;
    zsh[(sub*3 + 1)*64 + o] = ztv;
    zsh[(sub*3 + 2)*64 + o] = zcv;
    __syncthreads();
    #pragma unroll
    for (int kk = 0; kk < 3; kk++){
      float t = ba[o];
      #pragma unroll 16
      for (int d = 0; d < 64; d++) t = fmaf(Was[o*65 + d], zsh[(sub*3 + kk)*64 + d], t);
      t = tanhf(t) * qv[o];
      red[sub*64 + o] = t;
      __syncthreads();
      if (o < 32) red[sub*64 + o] += red[sub*64 + o + 32];
      __syncthreads();
      if (o < 32){
        float s = red[sub*64 + o];
        for (int off = 16; off > 0; off >>= 1) s += __shfl_down_sync(0xffffffffu, s, off);
        if (o == 0) sv[sub*3 + kk] = s;
      }
      __syncthreads();
    }
    if (o == 0){
      float m = fmaxf(sv[sub*3], fmaxf(sv[sub*3+1], sv[sub*3+2]));
      float e0 = expf(sv[sub*3]-m), e1 = expf(sv[sub*3+1]-m), e2 = expf(sv[sub*3+2]-m);
      float inv = 1.f/(e0+e1+e2);
      av[sub*3] = e0*inv; av[sub*3+1] = e1*inv; av[sub*3+2] = e2*inv;
    }
    __syncthreads();
    zag[sub*64 + o] = av[sub*3]*zfv + av[sub*3+1]*ztv + av[sub*3+2]*zcv;
    __syncthreads();
    if (o < 7){
      float v = b2[o];
      #pragma unroll 16
      for (int d = 0; d < 64; d++) v = fmaf(W2[o*64 + d], zag[sub*64 + d], v);
      out[row*7 + o] = v;
    }
    __syncthreads();
  }
}

// ============ 6. stage5: gram x3 (96) || att (128), fused final via ticket ============
__global__ __launch_bounds__(256) void k_stage5(const float* __restrict__ Wa, const float* __restrict__ ba,
                                                const float* __restrict__ q,  const float* __restrict__ W2,
                                                const float* __restrict__ b2, float* __restrict__ out){
  __shared__ __align__(16) float smem[5536];
  __shared__ unsigned int s_last;
  int b = blockIdx.x;
  int tid = threadIdx.x;
  if (b < 96){
    if (b < 64)      gram_role(0, b >> 3, b & 7, smem);
    else if (b < 80) gram_role(1, (b - 64) >> 2, (b - 64) & 3, smem);
    else             gram_role(2, (b - 80) >> 2, (b - 80) & 3, smem);
    __threadfence();
    __syncthreads();
    if (tid == 0) s_last = (atomicAdd(&g_ticket, 1u) == 95u) ? 1u : 0u;
    __syncthreads();
    if (s_last){
      if (tid == 0) g_ticket = 0u;
      __threadfence();
      double lc = 0.0, ld = 0.0;
      for (int e = tid; e < 128*128; e += 256){
        int a = e >> 7, bb = e & 127;
        double s = ((a < 64) == (bb < 64)) ? 1.0 : -1.0;
        double g = g_G[e];
        lc += s * g * g;
      }
      for (int e = tid; e < 64*64; e += 256){
        double m1 = g_M1[e]; ld += m1*m1;
        double m2 = g_M2[e]; ld += m2*m2;
      }
      double* s1 = (double*)smem;
      double* s2 = s1 + 256;
      s1[tid] = lc; s2[tid] = ld; __syncthreads();
      for (int o = 128; o > 0; o >>= 1){
        if (tid < o){ s1[tid] += s1[tid + o]; s2[tid] += s2[tid + o]; }
        __syncthreads();
      }
      if (tid == 0){
        out[N*7]     = (float)(s1[0] / ((double)N * (double)N));
        out[N*7 + 1] = (float)(s2[0] / (2047.0 * 2047.0));
      }
    }
  } else {
    att_role(b - 96, Wa, ba, q, W2, b2, out, smem);
  }
}

extern "C" void kernel_launch(void* const* d_in, const int* in_sizes, int n_in,
                              void* d_out, int out_size){
  const float* x   = (const float*)d_in[0];
  const float* A   = (const float*)d_in[1];
  const float* W1  = (const float*)d_in[3];
  const float* b1  = (const float*)d_in[4];
  const float* WF1 = (const float*)d_in[5];
  const float* bF1 = (const float*)d_in[6];
  const float* WF2 = (const float*)d_in[7];
  const float* bF2 = (const float*)d_in[8];
  const float* WT1 = (const float*)d_in[9];
  const float* bT1 = (const float*)d_in[10];
  const float* WT2 = (const float*)d_in[11];
  const float* bT2 = (const float*)d_in[12];
  const float* WC1 = (const float*)d_in[13];
  const float* bC1 = (const float*)d_in[14];
  const float* WC2 = (const float*)d_in[15];
  const float* bC2 = (const float*)d_in[16];
  const float* Wa  = (const float*)d_in[17];
  const float* ba  = (const float*)d_in[18];
  const float* q   = (const float*)d_in[19];
  const float* W2  = (const float*)d_in[20];
  const float* b2  = (const float*)d_in[21];
  float* out = (float*)d_out;

  k_pre   <<<N/16, 256>>>(A, x, W1, b1);
  k_stage1<<<1024, 256>>>(A);
  k_stage2<<<320,  256>>>(WT1, bT1, WC1, bC1);
  k_stage3<<<576,  256>>>(A, WF1, bF1, WC1, bC1);
  k_stage4<<<256,  256>>>(WT2, bT2, WF2, bF2, WC2, bC2);
  k_stage5<<<224,  256>>>(Wa, ba, q, W2, b2, out);
}

// round 14
// speedup vs baseline: 1.3295x; 1.2148x over previous
#include <cuda_runtime.h>
#include <cuda_bf16.h>
#include <math.h>
#include <stdint.h>

#define N 2048
#define H 64

typedef unsigned long long ull;

__device__ float g_dA[N];
__device__ float g_h[N*H];
__device__ float g_hn[N*H];
__device__ float g_hsq[N];
__device__ __nv_bfloat16 g_Ahi[N*N];
__device__ __nv_bfloat16 g_Alo[N*N];
__device__ __nv_bfloat16 g_BThi[H*N];
__device__ __nv_bfloat16 g_BTlo[H*N];
__device__ __nv_bfloat16 g_Z1Thi[2*H*N];
__device__ __nv_bfloat16 g_Z1Tlo[2*H*N];
__device__ float g_part[8*N*2*H];
__device__ float g_Z1f[N*2*H];
__device__ ull   g_cand[N*32];
__device__ int   g_idx[N*4];
__device__ float g_cval[N*4];
__device__ float g_dc[N];
__device__ float g_zf[N*H], g_zt[N*H], g_zcf[N*H], g_zct[N*H];
__device__ float g_Lcf[N*H], g_Lct[N*H];
__device__ double g_G[128*128];
__device__ double g_M1[64*64];
__device__ double g_M2[64*64];
__device__ unsigned int g_ticket;

__device__ __forceinline__ float leaky_f(float v){ return v > 0.f ? v : 0.1f*v; }

__device__ __forceinline__ unsigned int fmap(float v){
  unsigned int u = __float_as_uint(v);
  return (u & 0x80000000u) ? ~u : (u | 0x80000000u);
}

__device__ __forceinline__ void top4_insert(ull* t, ull key){
  if (key > t[3]) {
    t[3] = key;
    ull tmp;
    if (t[3] > t[2]) { tmp = t[2]; t[2] = t[3]; t[3] = tmp; }
    if (t[2] > t[1]) { tmp = t[1]; t[1] = t[2]; t[2] = tmp; }
    if (t[1] > t[0]) { tmp = t[0]; t[0] = t[1]; t[1] = tmp; }
  }
}

__device__ __forceinline__ ull pk2(float lo, float hi){
  ull r; asm("mov.b64 %0, {%1, %2};" : "=l"(r) : "f"(lo), "f"(hi)); return r;
}
__device__ __forceinline__ void upk2(ull v, float& lo, float& hi){
  asm("mov.b64 {%0, %1}, %2;" : "=f"(lo), "=f"(hi) : "l"(v));
}
__device__ __forceinline__ ull ffma2(ull a, ull b, ull c){
  ull r; asm("fma.rn.f32x2 %0, %1, %2, %3;" : "=l"(r) : "l"(a), "l"(b), "l"(c)); return r;
}
__device__ __forceinline__ uint32_t s2u(const void* p){
  uint32_t a;
  asm("{ .reg .u64 t; cvta.to.shared.u64 t, %1; cvt.u32.u64 %0, t; }" : "=r"(a) : "l"(p));
  return a;
}
__device__ __forceinline__ void ldsm4(uint32_t& r0, uint32_t& r1, uint32_t& r2, uint32_t& r3, uint32_t addr){
  asm volatile("ldmatrix.sync.aligned.m8n8.x4.shared.b16 {%0,%1,%2,%3}, [%4];"
               : "=r"(r0), "=r"(r1), "=r"(r2), "=r"(r3) : "r"(addr));
}
__device__ __forceinline__ void mma16816(float* d, uint32_t a0, uint32_t a1, uint32_t a2, uint32_t a3,
                                         uint32_t b0, uint32_t b1){
  asm volatile("mma.sync.aligned.m16n8k16.row.col.f32.bf16.bf16.f32 "
               "{%0,%1,%2,%3},{%4,%5,%6,%7},{%8,%9},{%0,%1,%2,%3};"
               : "+f"(d[0]), "+f"(d[1]), "+f"(d[2]), "+f"(d[3])
               : "r"(a0), "r"(a1), "r"(a2), "r"(a3), "r"(b0), "r"(b1));
}

// ============ 1. k_pre: rowsum(A) + A bf16 split + h + hn/hsq + BT split ============
__global__ __launch_bounds__(256) void k_pre(const float* __restrict__ A,
                                             const float* __restrict__ x,
                                             const float* __restrict__ W1,
                                             const float* __restrict__ b1){
  __shared__ float Ws[64][129];
  __shared__ float xs[16][128];
  __shared__ float hs[16][65];
  __shared__ float ss[16];
  __shared__ float das[16];
  int tid = threadIdx.x;
  int base = blockIdx.x * 16;
  for (int e = tid; e < 64*128; e += 256) Ws[e>>7][e&127] = W1[e];
  for (int e = tid; e < 16*128; e += 256) xs[e>>7][e&127] = x[(size_t)base*128 + e];
  {
    int w = tid >> 5, lane = tid & 31;
    int r0 = base + w*2;
    const float* p0 = A + (size_t)r0*N;
    const float* p1 = p0 + N;
    float s0 = 0.f, s1 = 0.f;
    for (int i = lane; i < N; i += 32){
      float v0 = p0[i], v1 = p1[i];
      s0 += v0; s1 += v1;
      __nv_bfloat16 h0 = __float2bfloat16(v0);
      __nv_bfloat16 h1 = __float2bfloat16(v1);
      g_Ahi[(size_t)r0*N + i]     = h0;
      g_Alo[(size_t)r0*N + i]     = __float2bfloat16(v0 - __bfloat162float(h0));
      g_Ahi[(size_t)(r0+1)*N + i] = h1;
      g_Alo[(size_t)(r0+1)*N + i] = __float2bfloat16(v1 - __bfloat162float(h1));
    }
    for (int o = 16; o > 0; o >>= 1){
      s0 += __shfl_down_sync(0xffffffffu, s0, o);
      s1 += __shfl_down_sync(0xffffffffu, s1, o);
    }
    if (lane == 0){
      float d0 = rsqrtf(s0 + 1e-10f), d1 = rsqrtf(s1 + 1e-10f);
      das[w*2] = d0; das[w*2+1] = d1;
      g_dA[r0] = d0; g_dA[r0+1] = d1;
    }
  }
  __syncthreads();
  int o = tid & 63, rg = tid >> 6;
  float hv[4];
  #pragma unroll
  for (int rr = 0; rr < 4; rr++){
    int rl = rg*4 + rr;
    float a = b1[o];
    #pragma unroll 16
    for (int d = 0; d < 128; d++) a = fmaf(Ws[o][d], xs[rl][d], a);
    hv[rr] = leaky_f(a);
    hs[rl][o] = hv[rr];
  }
  __syncthreads();
  if (tid < 16){
    float s = 0.f;
    #pragma unroll 8
    for (int d = 0; d < 64; d++) s = fmaf(hs[tid][d], hs[tid][d], s);
    ss[tid] = s;
    g_hsq[base + tid] = s;
  }
  __syncthreads();
  #pragma unroll
  for (int rr = 0; rr < 4; rr++){
    int rl = rg*4 + rr, row = base + rl;
    float rn = rsqrtf(ss[rl]);
    float v = hv[rr];
    g_h [row*64 + o] = v;
    g_hn[row*64 + o] = v*rn + 1e-10f;
    float hd = v * das[rl];
    __nv_bfloat16 bh = __float2bfloat16(hd);
    g_BThi[o*N + row] = bh;
    g_BTlo[o*N + row] = __float2bfloat16(hd - __bfloat162float(bh));
  }
}

// ============ HMMA gemm role: 128 rows x C cols, bf16-split, K-split 8 ============
// B operands are [n][k] (transposed), bf16 hi/lo. smem pitch = 12 words per 16-k tile row.
template<int C>
__device__ void gemm_mma_role(const __nv_bfloat16* __restrict__ BThi,
                              const __nv_bfloat16* __restrict__ BTlo,
                              int rowblk, int ksplit, uint32_t* pool){
  constexpr int NF = C / 8;                // n-frags per warp
  uint32_t* AhiS = pool;                   // 128 x 12 words
  uint32_t* AloS = pool + 1536;
  uint32_t* BhiS = pool + 3072;            // C x 12 words
  uint32_t* BloS = pool + 3072 + C*12;
  int tid = threadIdx.x, wid = tid >> 5, lane = tid & 31;
  int rowbase = rowblk * 128;
  int kwbase = ksplit * 128;               // word offset in k (256 k / 2)
  const uint32_t* Ahu = (const uint32_t*)g_Ahi;
  const uint32_t* Alu = (const uint32_t*)g_Alo;
  const uint32_t* Bhu = (const uint32_t*)BThi;
  const uint32_t* Blu = (const uint32_t*)BTlo;
  float D[NF][4];
  #pragma unroll
  for (int j = 0; j < NF; j++)
    #pragma unroll
    for (int q = 0; q < 4; q++) D[j][q] = 0.f;
  uint32_t sb = s2u(pool);
  uint32_t aRow = (uint32_t)(wid*16 + (lane & 7) + ((lane >> 3) & 1)*8);
  uint32_t aAddrHi = sb + (aRow*12 + (lane >> 4)*4)*4;
  uint32_t aAddrLo = aAddrHi + 1536*4;
  int bn = lane >> 2, bw = lane & 3;
  for (int kt = 0; kt < 16; kt++){
    __syncthreads();
    int kw = kwbase + kt*8;
    #pragma unroll
    for (int i = 0; i < 4; i++){
      int e = tid + i*256;
      int r = e >> 3, w = e & 7;
      AhiS[r*12 + w] = Ahu[(size_t)(rowbase + r)*1024 + kw + w];
      AloS[r*12 + w] = Alu[(size_t)(rowbase + r)*1024 + kw + w];
    }
    #pragma unroll
    for (int i = 0; i < C/32; i++){
      int e = tid + i*256;
      int n = e >> 3, w = e & 7;
      BhiS[n*12 + w] = Bhu[(size_t)n*1024 + kw + w];
      BloS[n*12 + w] = Blu[(size_t)n*1024 + kw + w];
    }
    __syncthreads();
    uint32_t ah0, ah1, ah2, ah3, al0, al1, al2, al3;
    ldsm4(ah0, ah1, ah2, ah3, aAddrHi);
    ldsm4(al0, al1, al2, al3, aAddrLo);
    #pragma unroll
    for (int j = 0; j < NF; j++){
      int bi = (j*8 + bn)*12 + bw;
      uint32_t bh0 = BhiS[bi], bh1 = BhiS[bi + 4];
      uint32_t bl0 = BloS[bi], bl1 = BloS[bi + 4];
      mma16816(D[j], ah0, ah1, ah2, ah3, bh0, bh1);
      mma16816(D[j], ah0, ah1, ah2, ah3, bl0, bl1);
      mma16816(D[j], al0, al1, al2, al3, bh0, bh1);
    }
  }
  float* dst = g_part + (size_t)ksplit * N * C;
  int row0 = rowbase + wid*16 + (lane >> 2);
  #pragma unroll
  for (int j = 0; j < NF; j++){
    int col = j*8 + (lane & 3)*2;
    dst[row0*C + col]         = D[j][0];
    dst[row0*C + col + 1]     = D[j][1];
    dst[(row0+8)*C + col]     = D[j][2];
    dst[(row0+8)*C + col + 1] = D[j][3];
  }
}

// ============ heat role (proven FFMA2 path) ============
__device__ void heat_role(int b, float* smem){
  int tid = threadIdx.x;
  float* As   = smem;
  float* Bsb[2] = {smem + 2176, smem + 6528};
  float* asq  = smem + 10880;
  float* bqb[2] = {smem + 10912, smem + 10976};
  int rowbase = (b & 63) * 32;
  int jsplit  = b >> 6;
  int jbase   = jsplit * 256;
  int r0 = (tid >> 4) * 2, c0 = (tid & 15) * 4;
  #pragma unroll
  for (int i = 0; i < 8; i++){
    int e = tid + i*256;
    As[(e & 63)*34 + (e >> 6)] = g_h[(rowbase + (e >> 6))*64 + (e & 63)];
  }
  if (tid < 32) asq[tid] = g_hsq[rowbase + tid];
  float rb[16], rq;
  #pragma unroll
  for (int i = 0; i < 16; i++){
    int e = tid + i*256;
    rb[i] = g_h[(jbase + (e >> 6))*64 + (e & 63)];
  }
  rq = (tid < 64) ? g_hsq[jbase + tid] : 0.f;
  #pragma unroll
  for (int i = 0; i < 16; i++){
    int e = tid + i*256;
    Bsb[0][(e & 63)*68 + (e >> 6)] = rb[i];
  }
  if (tid < 64) bqb[0][tid] = rq;
  __syncthreads();
  float asqr0 = asq[r0], asqr1 = asq[r0+1];
  ull t[2][4];
  #pragma unroll
  for (int i = 0; i < 2; i++)
    #pragma unroll
    for (int q = 0; q < 4; q++) t[i][q] = 0ull;
  for (int tile = 0; tile < 4; tile++){
    int cur = tile & 1;
    int jc = jbase + tile*64;
    if (tile < 3){
      int jn = jc + 64;
      #pragma unroll
      for (int i = 0; i < 16; i++){
        int e = tid + i*256;
        rb[i] = g_h[(jn + (e >> 6))*64 + (e & 63)];
      }
      rq = (tid < 64) ? g_hsq[jn + tid] : 0.f;
    }
    const float* Bs = Bsb[cur];
    const float* bsq = bqb[cur];
    ull acc[2][2] = {{0ull,0ull},{0ull,0ull}};
    #pragma unroll 8
    for (int kk = 0; kk < 64; kk++){
      float2 a2 = *(const float2*)&As[kk*34 + r0];
      ull avx = pk2(a2.x, a2.x);
      ull avy = pk2(a2.y, a2.y);
      ulonglong2 bv = *(const ulonglong2*)&Bs[kk*68 + c0];
      acc[0][0] = ffma2(avx, bv.x, acc[0][0]);
      acc[0][1] = ffma2(avx, bv.y, acc[0][1]);
      acc[1][0] = ffma2(avy, bv.x, acc[1][0]);
      acc[1][1] = ffma2(avy, bv.y, acc[1][1]);
    }
    float bq[4] = {bsq[c0], bsq[c0+1], bsq[c0+2], bsq[c0+3]};
    #pragma unroll
    for (int i = 0; i < 2; i++){
      float asqr = i ? asqr1 : asqr0;
      float d0, d1, d2, d3;
      upk2(acc[i][0], d0, d1);
      upk2(acc[i][1], d2, d3);
      float dd[4] = {d0, d1, d2, d3};
      #pragma unroll
      for (int j = 0; j < 4; j++){
        float dist = asqr + bq[j] - 2.f*dd[j] + 6.4e-9f;
        int jg = jc + c0 + j;
        ull key = ((ull)fmap(-dist) << 32) | (unsigned int)(2047 - jg);
        top4_insert(t[i], key);
      }
    }
    if (tile < 3){
      int nxt = 1 - cur;
      #pragma unroll
      for (int i = 0; i < 16; i++){
        int e = tid + i*256;
        Bsb[nxt][(e & 63)*68 + (e >> 6)] = rb[i];
      }
      if (tid < 64) bqb[nxt][tid] = rq;
    }
    __syncthreads();
  }
  ull* cand = (ull*)smem;
  __syncthreads();
  #pragma unroll
  for (int i = 0; i < 2; i++)
    #pragma unroll
    for (int q = 0; q < 4; q++)
      cand[(r0 + i)*64 + c0 + q] = t[i][q];
  __syncthreads();
  if (tid < 32){
    ull m[4] = {0ull,0ull,0ull,0ull};
    for (int e = 0; e < 64; e++) top4_insert(m, cand[tid*64 + e]);
    #pragma unroll
    for (int q = 0; q < 4; q++)
      g_cand[(rowbase + tid)*32 + jsplit*4 + q] = m[q];
  }
}

// ============ 2. stage1: heat (512) || gemm64 HMMA (128) ============
__global__ __launch_bounds__(256) void k_stage1(){
  __shared__ __align__(16) float pool[11040];
  int b = blockIdx.x;
  if (b < 512) heat_role(b, pool);
  else {
    int bb = b - 512;
    gemm_mma_role<64>(g_BThi, g_BTlo, bb & 15, bb >> 4, (uint32_t*)pool);
  }
}

// ============ z1t role (8-partial sum, writes Z1T bf16 split) ============
__device__ __forceinline__ void z1t_role(int rb, const float* __restrict__ WT1, const float* __restrict__ bT1,
                                         const float* __restrict__ WC1, const float* __restrict__ bC1, float* smem){
  float* Wa_ = smem;
  float* Wb_ = smem + 4160;
  float* ps  = smem + 8320;     // 32x65
  int tid = threadIdx.x; int sub = tid >> 6; int o = tid & 63;
  for (int e = tid; e < 4096; e += 256){
    Wa_[(e>>6)*65 + (e&63)] = WT1[e];
    Wb_[(e>>6)*65 + (e&63)] = WC1[e];
  }
  int base = rb*32 + sub*8;
  float das[8];
  #pragma unroll
  for (int r = 0; r < 8; r++){
    int row = base + r;
    float p = 0.f;
    #pragma unroll
    for (int s = 0; s < 8; s++) p += g_part[(size_t)s*N*64 + row*64 + o];
    das[r] = g_dA[row];
    ps[(sub*8 + r)*65 + o] = das[r] * p;
  }
  __syncthreads();
  float b1v = bT1[o], b2v = bC1[o];
  float a1[8], a2[8];
  #pragma unroll
  for (int r = 0; r < 8; r++){ a1[r] = b1v; a2[r] = b2v; }
  #pragma unroll 8
  for (int d = 0; d < 64; d++){
    float wa = Wa_[o*65 + d], wb = Wb_[o*65 + d];
    #pragma unroll
    for (int r = 0; r < 8; r++){
      float m = ps[(sub*8 + r)*65 + d];
      a1[r] = fmaf(wa, m, a1[r]);
      a2[r] = fmaf(wb, m, a2[r]);
    }
  }
  #pragma unroll
  for (int r = 0; r < 8; r++){
    int row = base + r;
    float v1 = das[r] * leaky_f(a1[r]);
    float v2 = das[r] * leaky_f(a2[r]);
    __nv_bfloat16 h1 = __float2bfloat16(v1);
    __nv_bfloat16 h2 = __float2bfloat16(v2);
    g_Z1Thi[o*N + row]        = h1;
    g_Z1Tlo[o*N + row]        = __float2bfloat16(v1 - __bfloat162float(h1));
    g_Z1Thi[(64 + o)*N + row] = h2;
    g_Z1Tlo[(64 + o)*N + row] = __float2bfloat16(v2 - __bfloat162float(h2));
  }
}

__device__ __forceinline__ void cos_role(int blk){
  int w = threadIdx.x >> 5;
  int lane = threadIdx.x & 31;
  int row = blk * 8 + w;
  ull t[4] = {0ull,0ull,0ull,0ull};
  t[0] = g_cand[row*32 + lane];
  #pragma unroll
  for (int off = 16; off >= 1; off >>= 1){
    ull r0 = __shfl_down_sync(0xffffffffu, t[0], off);
    ull r1 = __shfl_down_sync(0xffffffffu, t[1], off);
    ull r2 = __shfl_down_sync(0xffffffffu, t[2], off);
    ull r3 = __shfl_down_sync(0xffffffffu, t[3], off);
    top4_insert(t, r0); top4_insert(t, r1);
    top4_insert(t, r2); top4_insert(t, r3);
  }
  int idx[4];
  #pragma unroll
  for (int q = 0; q < 4; q++){
    ull k = __shfl_sync(0xffffffffu, t[q], 0);
    idx[q] = 2047 - (int)(unsigned int)(k & 0xFFFFFFFFull);
  }
  if (lane == 0){
    #pragma unroll
    for (int q = 0; q < 4; q++) g_idx[row*4 + q] = idx[q];
  }
  float c[4];
  #pragma unroll
  for (int q = 0; q < 4; q++){
    int j = idx[q];
    float s = g_hn[row*64 + lane]      * g_hn[j*64 + lane]
            + g_hn[row*64 + 32 + lane] * g_hn[j*64 + 32 + lane];
    for (int o = 16; o > 0; o >>= 1) s += __shfl_down_sync(0xffffffffu, s, o);
    c[q] = s;
  }
  if (lane == 0){
    float rs = c[0] + c[1] + c[2] + c[3];
    g_dc[row] = rsqrtf(rs + 1e-10f);
    #pragma unroll
    for (int q = 0; q < 4; q++) g_cval[row*4 + q] = c[q];
  }
}

// ============ 3. stage2: cos (256) || z1t (64) ============
__global__ __launch_bounds__(256) void k_stage2(const float* __restrict__ WT1, const float* __restrict__ bT1,
                                                const float* __restrict__ WC1, const float* __restrict__ bC1){
  __shared__ __align__(16) float smem[10400];
  int b = blockIdx.x;
  if (b < 256) cos_role(b);
  else z1t_role(b - 256, WT1, bT1, WC1, bC1, smem);
}

__device__ __forceinline__ void z1f_role(int rb, const float* __restrict__ WF1, const float* __restrict__ bF1,
                                         const float* __restrict__ WC1, const float* __restrict__ bC1, float* smem){
  float* Wa_ = smem;
  float* Wb_ = smem + 4160;
  float* ps  = smem + 8320;   // 32x65
  int tid = threadIdx.x; int sub = tid >> 6; int o = tid & 63;
  for (int e = tid; e < 4096; e += 256){
    Wa_[(e>>6)*65 + (e&63)] = WF1[e];
    Wb_[(e>>6)*65 + (e&63)] = WC1[e];
  }
  int base = rb*32 + sub*8;
  #pragma unroll
  for (int r = 0; r < 8; r++){
    int row = base + r;
    float dci = g_dc[row];
    float m = 0.f;
    #pragma unroll
    for (int t = 0; t < 4; t++){
      int j = g_idx[row*4 + t];
      float coef = g_cval[row*4 + t] * dci * g_dc[j];
      m = fmaf(coef, g_h[j*64 + o], m);
    }
    ps[(sub*8 + r)*65 + o] = m;
  }
  __syncthreads();
  float b1v = bF1[o], b2v = bC1[o];
  float a1[8], a2[8];
  #pragma unroll
  for (int r = 0; r < 8; r++){ a1[r] = b1v; a2[r] = b2v; }
  #pragma unroll 8
  for (int d = 0; d < 64; d++){
    float wa = Wa_[o*65 + d], wb = Wb_[o*65 + d];
    #pragma unroll
    for (int r = 0; r < 8; r++){
      float m = ps[(sub*8 + r)*65 + d];
      a1[r] = fmaf(wa, m, a1[r]);
      a2[r] = fmaf(wb, m, a2[r]);
    }
  }
  #pragma unroll
  for (int r = 0; r < 8; r++){
    int row = base + r;
    g_Z1f[row*128 + o]      = leaky_f(a1[r]);
    g_Z1f[row*128 + 64 + o] = leaky_f(a2[r]);
  }
}

// ============ 4. stage3: gemm128 HMMA (128) || z1f (64) ============
__global__ __launch_bounds__(256) void k_stage3(const float* __restrict__ WF1, const float* __restrict__ bF1,
                                                const float* __restrict__ WC1, const float* __restrict__ bC1){
  __shared__ __align__(16) float pool[10400];
  int b = blockIdx.x;
  if (b < 128) gemm_mma_role<128>(g_Z1Thi, g_Z1Tlo, b & 15, b >> 4, (uint32_t*)pool);
  else z1f_role(b - 128, WF1, bF1, WC1, bC1, pool);
}

__device__ __forceinline__ void z2t_role(int rb, const float* __restrict__ WT2, const float* __restrict__ bT2,
                                         const float* __restrict__ WC2, const float* __restrict__ bC2, float* smem){
  float* Wa_ = smem;
  float* Wb_ = smem + 4160;
  float* ps  = smem + 8320;   // 16x130
  float* red = smem + 10400;  // 4x64
  int tid = threadIdx.x; int sub = tid >> 6; int o = tid & 63;
  for (int e = tid; e < 4096; e += 256){
    Wa_[(e>>6)*65 + (e&63)] = WT2[e];
    Wb_[(e>>6)*65 + (e&63)] = WC2[e];
  }
  int base = rb*16 + sub*4;
  #pragma unroll
  for (int r = 0; r < 4; r++){
    int row = base + r;
    float da = g_dA[row];
    float pA = 0.f, pB = 0.f;
    #pragma unroll
    for (int s = 0; s < 8; s++){
      pA += g_part[(size_t)s*N*128 + row*128 + o];
      pB += g_part[(size_t)s*N*128 + row*128 + 64 + o];
    }
    ps[(sub*4 + r)*130 + o]      = da * pA;
    ps[(sub*4 + r)*130 + 64 + o] = da * pB;
  }
  __syncthreads();
  float b1v = bT2[o], b2v = bC2[o];
  float a1[4], a2[4];
  #pragma unroll
  for (int r = 0; r < 4; r++){ a1[r] = b1v; a2[r] = b2v; }
  #pragma unroll 8
  for (int d = 0; d < 64; d++){
    float wa = Wa_[o*65 + d], wb = Wb_[o*65 + d];
    #pragma unroll
    for (int r = 0; r < 4; r++){
      a1[r] = fmaf(wa, ps[(sub*4 + r)*130 + d],      a1[r]);
      a2[r] = fmaf(wb, ps[(sub*4 + r)*130 + 64 + d], a2[r]);
    }
  }
  #pragma unroll
  for (int r = 0; r < 4; r++){
    int row = base + r;
    float zt  = leaky_f(a1[r]);
    float zct = leaky_f(a2[r]);
    g_zt [row*64 + o] = zt;
    g_zct[row*64 + o] = zct;
    __syncthreads();
    red[sub*64 + o] = zct*zct;
    __syncthreads();
    for (int off = 32; off > 0; off >>= 1){
      if (o < off) red[sub*64 + o] += red[sub*64 + o + off];
      __syncthreads();
    }
    float mn = sqrtf(red[sub*64] * 0.015625f) + 1e-10f;
    g_Lct[row*64 + o] = zct / mn;
  }
}

__device__ __forceinline__ void z2f_role(int rb, const float* __restrict__ WF2, const float* __restrict__ bF2,
                                         const float* __restrict__ WC2, const float* __restrict__ bC2, float* smem){
  float* Wa_ = smem;
  float* Wb_ = smem + 4160;
  float* ps  = smem + 8320;
  float* red = smem + 10400;
  int tid = threadIdx.x; int sub = tid >> 6; int o = tid & 63;
  for (int e = tid; e < 4096; e += 256){
    Wa_[(e>>6)*65 + (e&63)] = WF2[e];
    Wb_[(e>>6)*65 + (e&63)] = WC2[e];
  }
  int base = rb*16 + sub*4;
  #pragma unroll
  for (int r = 0; r < 4; r++){
    int row = base + r;
    float dci = g_dc[row];
    float mf = 0.f, mc = 0.f;
    #pragma unroll
    for (int t = 0; t < 4; t++){
      int j = g_idx[row*4 + t];
      float coef = g_cval[row*4 + t] * dci * g_dc[j];
      mf = fmaf(coef, g_Z1f[j*128 + o],      mf);
      mc = fmaf(coef, g_Z1f[j*128 + 64 + o], mc);
    }
    ps[(sub*4 + r)*130 + o]      = mf;
    ps[(sub*4 + r)*130 + 64 + o] = mc;
  }
  __syncthreads();
  float b1v = bF2[o], b2v = bC2[o];
  float a1[4], a2[4];
  #pragma unroll
  for (int r = 0; r < 4; r++){ a1[r] = b1v; a2[r] = b2v; }
  #pragma unroll 8
  for (int d = 0; d < 64; d++){
    float wa = Wa_[o*65 + d], wb = Wb_[o*65 + d];
    #pragma unroll
    for (int r = 0; r < 4; r++){
      a1[r] = fmaf(wa, ps[(sub*4 + r)*130 + d],      a1[r]);
      a2[r] = fmaf(wb, ps[(sub*4 + r)*130 + 64 + d], a2[r]);
    }
  }
  #pragma unroll
  for (int r = 0; r < 4; r++){
    int row = base + r;
    float zf  = leaky_f(a1[r]);
    float zcf = leaky_f(a2[r]);
    g_zf [row*64 + o] = zf;
    g_zcf[row*64 + o] = zcf;
    __syncthreads();
    red[sub*64 + o] = zcf*zcf;
    __syncthreads();
    for (int off = 32; off > 0; off >>= 1){
      if (o < off) red[sub*64 + o] += red[sub*64 + o + off];
      __syncthreads();
    }
    float mn = sqrtf(red[sub*64] * 0.015625f) + 1e-10f;
    g_Lcf[row*64 + o] = zcf / mn;
  }
}

// ============ 5. stage4: z2t (128) || z2f (128) ============
__global__ __launch_bounds__(256) void k_stage4(const float* __restrict__ WT2, const float* __restrict__ bT2,
                                                const float* __restrict__ WF2, const float* __restrict__ bF2,
                                                const float* __restrict__ WC2, const float* __restrict__ bC2){
  __shared__ __align__(16) float smem[10656];
  int b = blockIdx.x;
  if (b < 128) z2t_role(b, WT2, bT2, WC2, bC2, smem);
  else z2f_role(b - 128, WF2, bF2, WC2, bC2, smem);
}

// ============ gram role ============
__device__ __forceinline__ void gram_role(int mode, int bx, int by, float* smem){
  float* As = smem;
  float* Bs = smem + 1088;
  float* mean = smem + 2176;
  const float *A0, *A1, *B0, *B1; double* out; int cb; int use_mean;
  if (mode == 0){ A0 = g_Lcf; A1 = g_Lct; B0 = g_Lcf; B1 = g_Lct; use_mean = 0; out = g_G; cb = 128; }
  else if (mode == 1){ A0 = g_zt; A1 = 0; B0 = g_zct; B1 = 0; use_mean = 1; out = g_M1; cb = 64; }
  else              { A0 = g_zf; A1 = 0; B0 = g_zcf; B1 = 0; use_mean = 1; out = g_M2; cb = 64; }
  int ci0 = bx * 16, cj0 = by * 16;
  const float* Ap = (ci0 < 64) ? A0 : A1; int ca_off = ci0 & 63;
  const float* Bp = (cj0 < 64) ? B0 : B1; int cb_off = cj0 & 63;
  int tid = threadIdx.x;
  int ty = tid >> 4, tx = tid & 15;
  if (use_mean){
    float s = 0.f;
    for (int r = ty; r < N; r += 16) s += Ap[r*64 + ca_off + tx];
    As[ty*17 + tx] = s;
    __syncthreads();
    if (ty == 0){
      float m = 0.f;
      #pragma unroll
      for (int k = 0; k < 16; k++) m += As[k*17 + tx];
      mean[tx] = m / (float)N;
    }
    __syncthreads();
  }
  double acc = 0.0; float f = 0.f;
  for (int n0 = 0; n0 < N; n0 += 64){
    __syncthreads();
    #pragma unroll
    for (int e = tid; e < 1024; e += 256){
      int r = n0 + (e >> 4);
      float av = Ap[r*64 + ca_off + (e & 15)];
      if (use_mean) av -= mean[e & 15];
      As[(e >> 4)*17 + (e & 15)] = av;
      Bs[(e >> 4)*17 + (e & 15)] = Bp[r*64 + cb_off + (e & 15)];
    }
    __syncthreads();
    #pragma unroll 16
    for (int r2 = 0; r2 < 64; r2++) f = fmaf(As[r2*17 + ty], Bs[r2*17 + tx], f);
    if (((n0 >> 6) & 1) == 1){ acc += (double)f; f = 0.f; }
  }
  out[(ci0 + ty)*cb + cj0 + tx] = acc;
}

__device__ __forceinline__ void att_role(int blk, const float* __restrict__ Wa, const float* __restrict__ ba,
                                         const float* __restrict__ q,  const float* __restrict__ W2,
                                         const float* __restrict__ b2, float* __restrict__ out, float* smem){
  float* Was = smem;
  float* qv  = smem + 4160;
  float* zsh = smem + 4224;
  float* red = smem + 4992;
  float* sv  = smem + 5248;
  float* av  = smem + 5260;
  float* zag = smem + 5272;
  int tid = threadIdx.x; int sub = tid >> 6; int o = tid & 63;
  for (int e = tid; e < 4096; e += 256) Was[(e>>6)*65 + (e&63)] = Wa[e];
  if (tid < 64) qv[tid] = q[tid];
  __syncthreads();
  for (int r = 0; r < 4; r++){
    int row = blk*16 + sub*4 + r;
    float zfv  = g_zf [row*64 + o];
    float ztv  = g_zt [row*64 + o];
    float zcv  = 0.5f*(g_zcf[row*64 + o] + g_zct[row*64 + o]);
    zsh[(sub*3 + 0)*64 + o] = zfv;
    zsh[(sub*3 + 1)*64 + o] = ztv;
    zsh[(sub*3 + 2)*64 + o] = zcv;
    __syncthreads();
    #pragma unroll
    for (int kk = 0; kk < 3; kk++){
      float t = ba[o];
      #pragma unroll 16
      for (int d = 0; d < 64; d++) t = fmaf(Was[o*65 + d], zsh[(sub*3 + kk)*64 + d], t);
      t = tanhf(t) * qv[o];
      red[sub*64 + o] = t;
      __syncthreads();
      if (o < 32) red[sub*64 + o] += red[sub*64 + o + 32];
      __syncthreads();
      if (o < 32){
        float s = red[sub*64 + o];
        for (int off = 16; off > 0; off >>= 1) s += __shfl_down_sync(0xffffffffu, s, off);
        if (o == 0) sv[sub*3 + kk] = s;
      }
      __syncthreads();
    }
    if (o == 0){
      float m = fmaxf(sv[sub*3], fmaxf(sv[sub*3+1], sv[sub*3+2]));
      float e0 = expf(sv[sub*3]-m), e1 = expf(sv[sub*3+1]-m), e2 = expf(sv[sub*3+2]-m);
      float inv = 1.f/(e0+e1+e2);
      av[sub*3] = e0*inv; av[sub*3+1] = e1*inv; av[sub*3+2] = e2*inv;
    }
    __syncthreads();
    zag[sub*64 + o] = av[sub*3]*zfv + av[sub*3+1]*ztv + av[sub*3+2]*zcv;
    __syncthreads();
    if (o < 7){
      float v = b2[o];
      #pragma unroll 16
      for (int d = 0; d < 64; d++) v = fmaf(W2[o*64 + d], zag[sub*64 + d], v);
      out[row*7 + o] = v;
    }
    __syncthreads();
  }
}

// ============ 6. stage5: gram x3 (96) || att (128), fused final ============
__global__ __launch_bounds__(256) void k_stage5(const float* __restrict__ Wa, const float* __restrict__ ba,
                                                const float* __restrict__ q,  const float* __restrict__ W2,
                                                const float* __restrict__ b2, float* __restrict__ out){
  __shared__ __align__(16) float smem[5536];
  __shared__ unsigned int s_last;
  int b = blockIdx.x;
  int tid = threadIdx.x;
  if (b < 96){
    if (b < 64)      gram_role(0, b >> 3, b & 7, smem);
    else if (b < 80) gram_role(1, (b - 64) >> 2, (b - 64) & 3, smem);
    else             gram_role(2, (b - 80) >> 2, (b - 80) & 3, smem);
    __threadfence();
    __syncthreads();
    if (tid == 0) s_last = (atomicAdd(&g_ticket, 1u) == 95u) ? 1u : 0u;
    __syncthreads();
    if (s_last){
      if (tid == 0) g_ticket = 0u;
      __threadfence();
      double lc = 0.0, ld = 0.0;
      for (int e = tid; e < 128*128; e += 256){
        int a = e >> 7, bb = e & 127;
        double s = ((a < 64) == (bb < 64)) ? 1.0 : -1.0;
        double g = g_G[e];
        lc += s * g * g;
      }
      for (int e = tid; e < 64*64; e += 256){
        double m1 = g_M1[e]; ld += m1*m1;
        double m2 = g_M2[e]; ld += m2*m2;
      }
      double* s1 = (double*)smem;
      double* s2 = s1 + 256;
      s1[tid] = lc; s2[tid] = ld; __syncthreads();
      for (int o = 128; o > 0; o >>= 1){
        if (tid < o){ s1[tid] += s1[tid + o]; s2[tid] += s2[tid + o]; }
        __syncthreads();
      }
      if (tid == 0){
        out[N*7]     = (float)(s1[0] / ((double)N * (double)N));
        out[N*7 + 1] = (float)(s2[0] / (2047.0 * 2047.0));
      }
    }
  } else {
    att_role(b - 96, Wa, ba, q, W2, b2, out, smem);
  }
}

extern "C" void kernel_launch(void* const* d_in, const int* in_sizes, int n_in,
                              void* d_out, int out_size){
  const float* x   = (const float*)d_in[0];
  const float* A   = (const float*)d_in[1];
  const float* W1  = (const float*)d_in[3];
  const float* b1  = (const float*)d_in[4];
  const float* WF1 = (const float*)d_in[5];
  const float* bF1 = (const float*)d_in[6];
  const float* WF2 = (const float*)d_in[7];
  const float* bF2 = (const float*)d_in[8];
  const float* WT1 = (const float*)d_in[9];
  const float* bT1 = (const float*)d_in[10];
  const float* WT2 = (const float*)d_in[11];
  const float* bT2 = (const float*)d_in[12];
  const float* WC1 = (const float*)d_in[13];
  const float* bC1 = (const float*)d_in[14];
  const float* WC2 = (const float*)d_in[15];
  const float* bC2 = (const float*)d_in[16];
  const float* Wa  = (const float*)d_in[17];
  const float* ba  = (const float*)d_in[18];
  const float* q   = (const float*)d_in[19];
  const float* W2  = (const float*)d_in[20];
  const float* b2  = (const float*)d_in[21];
  float* out = (float*)d_out;

  k_pre   <<<N/16, 256>>>(A, x, W1, b1);
  k_stage1<<<640,  256>>>();
  k_stage2<<<320,  256>>>(WT1, bT1, WC1, bC1);
  k_stage3<<<192,  256>>>(WF1, bF1, WC1, bC1);
  k_stage4<<<256,  256>>>(WT2, bT2, WF2, bF2, WC2, bC2);
  k_stage5<<<224,  256>>>(Wa, ba, q, W2, b2, out);
}

// round 15
// speedup vs baseline: 1.3803x; 1.0382x over previous
#include <cuda_runtime.h>
#include <cuda_bf16.h>
#include <math.h>
#include <stdint.h>

#define N 2048
#define H 64

typedef unsigned long long ull;

__device__ float g_dA[N];
__device__ float g_h[N*H];
__device__ float g_hn[N*H];
__device__ float g_hsq[N];
__device__ __nv_bfloat16 g_Ahi[N*N];
__device__ __nv_bfloat16 g_Alo[N*N];
__device__ __nv_bfloat16 g_BThi[H*N];
__device__ __nv_bfloat16 g_BTlo[H*N];
__device__ __nv_bfloat16 g_Z1Thi[2*H*N];
__device__ __nv_bfloat16 g_Z1Tlo[2*H*N];
__device__ float g_part[16*N*2*H];
__device__ float g_Z1f[N*2*H];
__device__ ull   g_cand[N*32];
__device__ int   g_idx[N*4];
__device__ float g_cval[N*4];
__device__ float g_dc[N];
__device__ float g_zf[N*H], g_zt[N*H], g_zcf[N*H], g_zct[N*H];
__device__ float g_Lcf[N*H], g_Lct[N*H];
__device__ double g_G[128*128];
__device__ double g_M1[64*64];
__device__ double g_M2[64*64];
__device__ unsigned int g_ticket;

__device__ __forceinline__ float leaky_f(float v){ return v > 0.f ? v : 0.1f*v; }

__device__ __forceinline__ unsigned int fmap(float v){
  unsigned int u = __float_as_uint(v);
  return (u & 0x80000000u) ? ~u : (u | 0x80000000u);
}

__device__ __forceinline__ void top4_insert(ull* t, ull key){
  if (key > t[3]) {
    t[3] = key;
    ull tmp;
    if (t[3] > t[2]) { tmp = t[2]; t[2] = t[3]; t[3] = tmp; }
    if (t[2] > t[1]) { tmp = t[1]; t[1] = t[2]; t[2] = tmp; }
    if (t[1] > t[0]) { tmp = t[0]; t[0] = t[1]; t[1] = tmp; }
  }
}

__device__ __forceinline__ ull pk2(float lo, float hi){
  ull r; asm("mov.b64 %0, {%1, %2};" : "=l"(r) : "f"(lo), "f"(hi)); return r;
}
__device__ __forceinline__ void upk2(ull v, float& lo, float& hi){
  asm("mov.b64 {%0, %1}, %2;" : "=f"(lo), "=f"(hi) : "l"(v));
}
__device__ __forceinline__ ull ffma2(ull a, ull b, ull c){
  ull r; asm("fma.rn.f32x2 %0, %1, %2, %3;" : "=l"(r) : "l"(a), "l"(b), "l"(c)); return r;
}
__device__ __forceinline__ uint32_t s2u(const void* p){
  uint32_t a;
  asm("{ .reg .u64 t; cvta.to.shared.u64 t, %1; cvt.u32.u64 %0, t; }" : "=r"(a) : "l"(p));
  return a;
}
__device__ __forceinline__ void ldsm4(uint32_t& r0, uint32_t& r1, uint32_t& r2, uint32_t& r3, uint32_t addr){
  asm volatile("ldmatrix.sync.aligned.m8n8.x4.shared.b16 {%0,%1,%2,%3}, [%4];"
               : "=r"(r0), "=r"(r1), "=r"(r2), "=r"(r3) : "r"(addr));
}
__device__ __forceinline__ void mma16816(float* d, uint32_t a0, uint32_t a1, uint32_t a2, uint32_t a3,
                                         uint32_t b0, uint32_t b1){
  asm volatile("mma.sync.aligned.m16n8k16.row.col.f32.bf16.bf16.f32 "
               "{%0,%1,%2,%3},{%4,%5,%6,%7},{%8,%9},{%0,%1,%2,%3};"
               : "+f"(d[0]), "+f"(d[1]), "+f"(d[2]), "+f"(d[3])
               : "r"(a0), "r"(a1), "r"(a2), "r"(a3), "r"(b0), "r"(b1));
}

// ============ 1. k_pre: rowsum(A) + A bf16 split + h + hn/hsq + BT split ============
__global__ __launch_bounds__(256) void k_pre(const float* __restrict__ A,
                                             const float* __restrict__ x,
                                             const float* __restrict__ W1,
                                             const float* __restrict__ b1){
  __shared__ float Ws[64][129];
  __shared__ float xs[16][128];
  __shared__ float hs[16][65];
  __shared__ float ss[16];
  __shared__ float das[16];
  int tid = threadIdx.x;
  int base = blockIdx.x * 16;
  for (int e = tid; e < 64*128; e += 256) Ws[e>>7][e&127] = W1[e];
  for (int e = tid; e < 16*128; e += 256) xs[e>>7][e&127] = x[(size_t)base*128 + e];
  {
    int w = tid >> 5, lane = tid & 31;
    int r0 = base + w*2;
    const float* p0 = A + (size_t)r0*N;
    const float* p1 = p0 + N;
    float s0 = 0.f, s1 = 0.f;
    for (int i = lane; i < N; i += 32){
      float v0 = p0[i], v1 = p1[i];
      s0 += v0; s1 += v1;
      __nv_bfloat16 h0 = __float2bfloat16(v0);
      __nv_bfloat16 h1 = __float2bfloat16(v1);
      g_Ahi[(size_t)r0*N + i]     = h0;
      g_Alo[(size_t)r0*N + i]     = __float2bfloat16(v0 - __bfloat162float(h0));
      g_Ahi[(size_t)(r0+1)*N + i] = h1;
      g_Alo[(size_t)(r0+1)*N + i] = __float2bfloat16(v1 - __bfloat162float(h1));
    }
    for (int o = 16; o > 0; o >>= 1){
      s0 += __shfl_down_sync(0xffffffffu, s0, o);
      s1 += __shfl_down_sync(0xffffffffu, s1, o);
    }
    if (lane == 0){
      float d0 = rsqrtf(s0 + 1e-10f), d1 = rsqrtf(s1 + 1e-10f);
      das[w*2] = d0; das[w*2+1] = d1;
      g_dA[r0] = d0; g_dA[r0+1] = d1;
    }
  }
  __syncthreads();
  int o = tid & 63, rg = tid >> 6;
  float hv[4];
  #pragma unroll
  for (int rr = 0; rr < 4; rr++){
    int rl = rg*4 + rr;
    float a = b1[o];
    #pragma unroll 16
    for (int d = 0; d < 128; d++) a = fmaf(Ws[o][d], xs[rl][d], a);
    hv[rr] = leaky_f(a);
    hs[rl][o] = hv[rr];
  }
  __syncthreads();
  if (tid < 16){
    float s = 0.f;
    #pragma unroll 8
    for (int d = 0; d < 64; d++) s = fmaf(hs[tid][d], hs[tid][d], s);
    ss[tid] = s;
    g_hsq[base + tid] = s;
  }
  __syncthreads();
  #pragma unroll
  for (int rr = 0; rr < 4; rr++){
    int rl = rg*4 + rr, row = base + rl;
    float rn = rsqrtf(ss[rl]);
    float v = hv[rr];
    g_h [row*64 + o] = v;
    g_hn[row*64 + o] = v*rn + 1e-10f;
    float hd = v * das[rl];
    __nv_bfloat16 bh = __float2bfloat16(hd);
    g_BThi[o*N + row] = bh;
    g_BTlo[o*N + row] = __float2bfloat16(hd - __bfloat162float(bh));
  }
}

// ============ HMMA gemm role: 128 rows x C cols, bf16-split, K-split 16 ============
template<int C>
__device__ void gemm_mma_role(const __nv_bfloat16* __restrict__ BThi,
                              const __nv_bfloat16* __restrict__ BTlo,
                              int rowblk, int ksplit, uint32_t* pool){
  constexpr int NF = C / 8;
  uint32_t* AhiS = pool;                   // 128 x 12 words
  uint32_t* AloS = pool + 1536;
  uint32_t* BhiS = pool + 3072;            // C x 12 words
  uint32_t* BloS = pool + 3072 + C*12;
  int tid = threadIdx.x, wid = tid >> 5, lane = tid & 31;
  int rowbase = rowblk * 128;
  int kwbase = ksplit * 64;                // 128 k per split = 64 words
  const uint32_t* Ahu = (const uint32_t*)g_Ahi;
  const uint32_t* Alu = (const uint32_t*)g_Alo;
  const uint32_t* Bhu = (const uint32_t*)BThi;
  const uint32_t* Blu = (const uint32_t*)BTlo;
  float D[NF][4];
  #pragma unroll
  for (int j = 0; j < NF; j++)
    #pragma unroll
    for (int q = 0; q < 4; q++) D[j][q] = 0.f;
  uint32_t sb = s2u(pool);
  uint32_t aRow = (uint32_t)(wid*16 + (lane & 7) + ((lane >> 3) & 1)*8);
  uint32_t aAddrHi = sb + (aRow*12 + (lane >> 4)*4)*4;
  uint32_t aAddrLo = aAddrHi + 1536*4;
  int bn = lane >> 2, bw = lane & 3;
  for (int kt = 0; kt < 8; kt++){
    __syncthreads();
    int kw = kwbase + kt*8;
    #pragma unroll
    for (int i = 0; i < 4; i++){
      int e = tid + i*256;
      int r = e >> 3, w = e & 7;
      AhiS[r*12 + w] = Ahu[(size_t)(rowbase + r)*1024 + kw + w];
      AloS[r*12 + w] = Alu[(size_t)(rowbase + r)*1024 + kw + w];
    }
    #pragma unroll
    for (int i = 0; i < C/32; i++){
      int e = tid + i*256;
      int n = e >> 3, w = e & 7;
      BhiS[n*12 + w] = Bhu[(size_t)n*1024 + kw + w];
      BloS[n*12 + w] = Blu[(size_t)n*1024 + kw + w];
    }
    __syncthreads();
    uint32_t ah0, ah1, ah2, ah3, al0, al1, al2, al3;
    ldsm4(ah0, ah1, ah2, ah3, aAddrHi);
    ldsm4(al0, al1, al2, al3, aAddrLo);
    #pragma unroll
    for (int j = 0; j < NF; j++){
      int bi = (j*8 + bn)*12 + bw;
      uint32_t bh0 = BhiS[bi], bh1 = BhiS[bi + 4];
      uint32_t bl0 = BloS[bi], bl1 = BloS[bi + 4];
      mma16816(D[j], ah0, ah1, ah2, ah3, bh0, bh1);
      mma16816(D[j], ah0, ah1, ah2, ah3, bl0, bl1);
      mma16816(D[j], al0, al1, al2, al3, bh0, bh1);
    }
  }
  float* dst = g_part + (size_t)ksplit * N * C;
  int row0 = rowbase + wid*16 + (lane >> 2);
  #pragma unroll
  for (int j = 0; j < NF; j++){
    int col = j*8 + (lane & 3)*2;
    dst[row0*C + col]         = D[j][0];
    dst[row0*C + col + 1]     = D[j][1];
    dst[(row0+8)*C + col]     = D[j][2];
    dst[(row0+8)*C + col + 1] = D[j][3];
  }
}

// ============ heat role (proven FFMA2 path) ============
__device__ void heat_role(int b, float* smem){
  int tid = threadIdx.x;
  float* As   = smem;
  float* Bsb[2] = {smem + 2176, smem + 6528};
  float* asq  = smem + 10880;
  float* bqb[2] = {smem + 10912, smem + 10976};
  int rowbase = (b & 63) * 32;
  int jsplit  = b >> 6;
  int jbase   = jsplit * 256;
  int r0 = (tid >> 4) * 2, c0 = (tid & 15) * 4;
  #pragma unroll
  for (int i = 0; i < 8; i++){
    int e = tid + i*256;
    As[(e & 63)*34 + (e >> 6)] = g_h[(rowbase + (e >> 6))*64 + (e & 63)];
  }
  if (tid < 32) asq[tid] = g_hsq[rowbase + tid];
  float rb[16], rq;
  #pragma unroll
  for (int i = 0; i < 16; i++){
    int e = tid + i*256;
    rb[i] = g_h[(jbase + (e >> 6))*64 + (e & 63)];
  }
  rq = (tid < 64) ? g_hsq[jbase + tid] : 0.f;
  #pragma unroll
  for (int i = 0; i < 16; i++){
    int e = tid + i*256;
    Bsb[0][(e & 63)*68 + (e >> 6)] = rb[i];
  }
  if (tid < 64) bqb[0][tid] = rq;
  __syncthreads();
  float asqr0 = asq[r0], asqr1 = asq[r0+1];
  ull t[2][4];
  #pragma unroll
  for (int i = 0; i < 2; i++)
    #pragma unroll
    for (int q = 0; q < 4; q++) t[i][q] = 0ull;
  for (int tile = 0; tile < 4; tile++){
    int cur = tile & 1;
    int jc = jbase + tile*64;
    if (tile < 3){
      int jn = jc + 64;
      #pragma unroll
      for (int i = 0; i < 16; i++){
        int e = tid + i*256;
        rb[i] = g_h[(jn + (e >> 6))*64 + (e & 63)];
      }
      rq = (tid < 64) ? g_hsq[jn + tid] : 0.f;
    }
    const float* Bs = Bsb[cur];
    const float* bsq = bqb[cur];
    ull acc[2][2] = {{0ull,0ull},{0ull,0ull}};
    #pragma unroll 8
    for (int kk = 0; kk < 64; kk++){
      float2 a2 = *(const float2*)&As[kk*34 + r0];
      ull avx = pk2(a2.x, a2.x);
      ull avy = pk2(a2.y, a2.y);
      ulonglong2 bv = *(const ulonglong2*)&Bs[kk*68 + c0];
      acc[0][0] = ffma2(avx, bv.x, acc[0][0]);
      acc[0][1] = ffma2(avx, bv.y, acc[0][1]);
      acc[1][0] = ffma2(avy, bv.x, acc[1][0]);
      acc[1][1] = ffma2(avy, bv.y, acc[1][1]);
    }
    float bq[4] = {bsq[c0], bsq[c0+1], bsq[c0+2], bsq[c0+3]};
    #pragma unroll
    for (int i = 0; i < 2; i++){
      float asqr = i ? asqr1 : asqr0;
      float d0, d1, d2, d3;
      upk2(acc[i][0], d0, d1);
      upk2(acc[i][1], d2, d3);
      float dd[4] = {d0, d1, d2, d3};
      #pragma unroll
      for (int j = 0; j < 4; j++){
        float dist = asqr + bq[j] - 2.f*dd[j] + 6.4e-9f;
        int jg = jc + c0 + j;
        ull key = ((ull)fmap(-dist) << 32) | (unsigned int)(2047 - jg);
        top4_insert(t[i], key);
      }
    }
    if (tile < 3){
      int nxt = 1 - cur;
      #pragma unroll
      for (int i = 0; i < 16; i++){
        int e = tid + i*256;
        Bsb[nxt][(e & 63)*68 + (e >> 6)] = rb[i];
      }
      if (tid < 64) bqb[nxt][tid] = rq;
    }
    __syncthreads();
  }
  ull* cand = (ull*)smem;
  __syncthreads();
  #pragma unroll
  for (int i = 0; i < 2; i++)
    #pragma unroll
    for (int q = 0; q < 4; q++)
      cand[(r0 + i)*64 + c0 + q] = t[i][q];
  __syncthreads();
  if (tid < 32){
    ull m[4] = {0ull,0ull,0ull,0ull};
    for (int e = 0; e < 64; e++) top4_insert(m, cand[tid*64 + e]);
    #pragma unroll
    for (int q = 0; q < 4; q++)
      g_cand[(rowbase + tid)*32 + jsplit*4 + q] = m[q];
  }
}

// ============ 2. stage1: heat (512) || gemm64 HMMA (256) ============
__global__ __launch_bounds__(256) void k_stage1(){
  __shared__ __align__(16) float pool[11040];
  int b = blockIdx.x;
  if (b < 512) heat_role(b, pool);
  else {
    int bb = b - 512;
    gemm_mma_role<64>(g_BThi, g_BTlo, bb & 15, bb >> 4, (uint32_t*)pool);
  }
}

// ============ z1t role (16-partial sum, writes Z1T bf16 split) ============
__device__ __forceinline__ void z1t_role(int rb, const float* __restrict__ WT1, const float* __restrict__ bT1,
                                         const float* __restrict__ WC1, const float* __restrict__ bC1, float* smem){
  float* Wa_ = smem;
  float* Wb_ = smem + 4160;
  float* ps  = smem + 8320;     // 32x65
  int tid = threadIdx.x; int sub = tid >> 6; int o = tid & 63;
  for (int e = tid; e < 4096; e += 256){
    Wa_[(e>>6)*65 + (e&63)] = WT1[e];
    Wb_[(e>>6)*65 + (e&63)] = WC1[e];
  }
  int base = rb*32 + sub*8;
  float das[8];
  #pragma unroll
  for (int r = 0; r < 8; r++){
    int row = base + r;
    float p = 0.f;
    #pragma unroll
    for (int s = 0; s < 16; s++) p += g_part[(size_t)s*N*64 + row*64 + o];
    das[r] = g_dA[row];
    ps[(sub*8 + r)*65 + o] = das[r] * p;
  }
  __syncthreads();
  float b1v = bT1[o], b2v = bC1[o];
  float a1[8], a2[8];
  #pragma unroll
  for (int r = 0; r < 8; r++){ a1[r] = b1v; a2[r] = b2v; }
  #pragma unroll 8
  for (int d = 0; d < 64; d++){
    float wa = Wa_[o*65 + d], wb = Wb_[o*65 + d];
    #pragma unroll
    for (int r = 0; r < 8; r++){
      float m = ps[(sub*8 + r)*65 + d];
      a1[r] = fmaf(wa, m, a1[r]);
      a2[r] = fmaf(wb, m, a2[r]);
    }
  }
  #pragma unroll
  for (int r = 0; r < 8; r++){
    int row = base + r;
    float v1 = das[r] * leaky_f(a1[r]);
    float v2 = das[r] * leaky_f(a2[r]);
    __nv_bfloat16 h1 = __float2bfloat16(v1);
    __nv_bfloat16 h2 = __float2bfloat16(v2);
    g_Z1Thi[o*N + row]        = h1;
    g_Z1Tlo[o*N + row]        = __float2bfloat16(v1 - __bfloat162float(h1));
    g_Z1Thi[(64 + o)*N + row] = h2;
    g_Z1Tlo[(64 + o)*N + row] = __float2bfloat16(v2 - __bfloat162float(h2));
  }
}

__device__ __forceinline__ void cos_role(int blk){
  int w = threadIdx.x >> 5;
  int lane = threadIdx.x & 31;
  int row = blk * 8 + w;
  ull t[4] = {0ull,0ull,0ull,0ull};
  t[0] = g_cand[row*32 + lane];
  #pragma unroll
  for (int off = 16; off >= 1; off >>= 1){
    ull r0 = __shfl_down_sync(0xffffffffu, t[0], off);
    ull r1 = __shfl_down_sync(0xffffffffu, t[1], off);
    ull r2 = __shfl_down_sync(0xffffffffu, t[2], off);
    ull r3 = __shfl_down_sync(0xffffffffu, t[3], off);
    top4_insert(t, r0); top4_insert(t, r1);
    top4_insert(t, r2); top4_insert(t, r3);
  }
  int idx[4];
  #pragma unroll
  for (int q = 0; q < 4; q++){
    ull k = __shfl_sync(0xffffffffu, t[q], 0);
    idx[q] = 2047 - (int)(unsigned int)(k & 0xFFFFFFFFull);
  }
  if (lane == 0){
    #pragma unroll
    for (int q = 0; q < 4; q++) g_idx[row*4 + q] = idx[q];
  }
  float c[4];
  #pragma unroll
  for (int q = 0; q < 4; q++){
    int j = idx[q];
    float s = g_hn[row*64 + lane]      * g_hn[j*64 + lane]
            + g_hn[row*64 + 32 + lane] * g_hn[j*64 + 32 + lane];
    for (int o = 16; o > 0; o >>= 1) s += __shfl_down_sync(0xffffffffu, s, o);
    c[q] = s;
  }
  if (lane == 0){
    float rs = c[0] + c[1] + c[2] + c[3];
    g_dc[row] = rsqrtf(rs + 1e-10f);
    #pragma unroll
    for (int q = 0; q < 4; q++) g_cval[row*4 + q] = c[q];
  }
}

// ============ 3. stage2: cos (256) || z1t (64) ============
__global__ __launch_bounds__(256) void k_stage2(const float* __restrict__ WT1, const float* __restrict__ bT1,
                                                const float* __restrict__ WC1, const float* __restrict__ bC1){
  __shared__ __align__(16) float smem[10400];
  int b = blockIdx.x;
  if (b < 256) cos_role(b);
  else z1t_role(b - 256, WT1, bT1, WC1, bC1, smem);
}

__device__ __forceinline__ void z1f_role(int rb, const float* __restrict__ WF1, const float* __restrict__ bF1,
                                         const float* __restrict__ WC1, const float* __restrict__ bC1, float* smem){
  float* Wa_ = smem;
  float* Wb_ = smem + 4160;
  float* ps  = smem + 8320;   // 32x65
  int tid = threadIdx.x; int sub = tid >> 6; int o = tid & 63;
  for (int e = tid; e < 4096; e += 256){
    Wa_[(e>>6)*65 + (e&63)] = WF1[e];
    Wb_[(e>>6)*65 + (e&63)] = WC1[e];
  }
  int base = rb*32 + sub*8;
  #pragma unroll
  for (int r = 0; r < 8; r++){
    int row = base + r;
    float dci = g_dc[row];
    float m = 0.f;
    #pragma unroll
    for (int t = 0; t < 4; t++){
      int j = g_idx[row*4 + t];
      float coef = g_cval[row*4 + t] * dci * g_dc[j];
      m = fmaf(coef, g_h[j*64 + o], m);
    }
    ps[(sub*8 + r)*65 + o] = m;
  }
  __syncthreads();
  float b1v = bF1[o], b2v = bC1[o];
  float a1[8], a2[8];
  #pragma unroll
  for (int r = 0; r < 8; r++){ a1[r] = b1v; a2[r] = b2v; }
  #pragma unroll 8
  for (int d = 0; d < 64; d++){
    float wa = Wa_[o*65 + d], wb = Wb_[o*65 + d];
    #pragma unroll
    for (int r = 0; r < 8; r++){
      float m = ps[(sub*8 + r)*65 + d];
      a1[r] = fmaf(wa, m, a1[r]);
      a2[r] = fmaf(wb, m, a2[r]);
    }
  }
  #pragma unroll
  for (int r = 0; r < 8; r++){
    int row = base + r;
    g_Z1f[row*128 + o]      = leaky_f(a1[r]);
    g_Z1f[row*128 + 64 + o] = leaky_f(a2[r]);
  }
}

// ============ 4. stage3: gemm128 HMMA (256) || z1f (64) ============
__global__ __launch_bounds__(256) void k_stage3(const float* __restrict__ WF1, const float* __restrict__ bF1,
                                                const float* __restrict__ WC1, const float* __restrict__ bC1){
  __shared__ __align__(16) float pool[10400];
  int b = blockIdx.x;
  if (b < 256) gemm_mma_role<128>(g_Z1Thi, g_Z1Tlo, b & 15, b >> 4, (uint32_t*)pool);
  else z1f_role(b - 256, WF1, bF1, WC1, bC1, pool);
}

__device__ __forceinline__ void z2t_role(int rb, const float* __restrict__ WT2, const float* __restrict__ bT2,
                                         const float* __restrict__ WC2, const float* __restrict__ bC2, float* smem){
  float* Wa_ = smem;
  float* Wb_ = smem + 4160;
  float* ps  = smem + 8320;   // 16x130
  float* red = smem + 10400;  // 4x64
  int tid = threadIdx.x; int sub = tid >> 6; int o = tid & 63;
  for (int e = tid; e < 4096; e += 256){
    Wa_[(e>>6)*65 + (e&63)] = WT2[e];
    Wb_[(e>>6)*65 + (e&63)] = WC2[e];
  }
  int base = rb*16 + sub*4;
  #pragma unroll
  for (int r = 0; r < 4; r++){
    int row = base + r;
    float da = g_dA[row];
    float pA = 0.f, pB = 0.f;
    #pragma unroll
    for (int s = 0; s < 16; s++){
      pA += g_part[(size_t)s*N*128 + row*128 + o];
      pB += g_part[(size_t)s*N*128 + row*128 + 64 + o];
    }
    ps[(sub*4 + r)*130 + o]      = da * pA;
    ps[(sub*4 + r)*130 + 64 + o] = da * pB;
  }
  __syncthreads();
  float b1v = bT2[o], b2v = bC2[o];
  float a1[4], a2[4];
  #pragma unroll
  for (int r = 0; r < 4; r++){ a1[r] = b1v; a2[r] = b2v; }
  #pragma unroll 8
  for (int d = 0; d < 64; d++){
    float wa = Wa_[o*65 + d], wb = Wb_[o*65 + d];
    #pragma unroll
    for (int r = 0; r < 4; r++){
      a1[r] = fmaf(wa, ps[(sub*4 + r)*130 + d],      a1[r]);
      a2[r] = fmaf(wb, ps[(sub*4 + r)*130 + 64 + d], a2[r]);
    }
  }
  #pragma unroll
  for (int r = 0; r < 4; r++){
    int row = base + r;
    float zt  = leaky_f(a1[r]);
    float zct = leaky_f(a2[r]);
    g_zt [row*64 + o] = zt;
    g_zct[row*64 + o] = zct;
    __syncthreads();
    red[sub*64 + o] = zct*zct;
    __syncthreads();
    for (int off = 32; off > 0; off >>= 1){
      if (o < off) red[sub*64 + o] += red[sub*64 + o + off];
      __syncthreads();
    }
    float mn = sqrtf(red[sub*64] * 0.015625f) + 1e-10f;
    g_Lct[row*64 + o] = zct / mn;
  }
}

__device__ __forceinline__ void z2f_role(int rb, const float* __restrict__ WF2, const float* __restrict__ bF2,
                                         const float* __restrict__ WC2, const float* __restrict__ bC2, float* smem){
  float* Wa_ = smem;
  float* Wb_ = smem + 4160;
  float* ps  = smem + 8320;
  float* red = smem + 10400;
  int tid = threadIdx.x; int sub = tid >> 6; int o = tid & 63;
  for (int e = tid; e < 4096; e += 256){
    Wa_[(e>>6)*65 + (e&63)] = WF2[e];
    Wb_[(e>>6)*65 + (e&63)] = WC2[e];
  }
  int base = rb*16 + sub*4;
  #pragma unroll
  for (int r = 0; r < 4; r++){
    int row = base + r;
    float dci = g_dc[row];
    float mf = 0.f, mc = 0.f;
    #pragma unroll
    for (int t = 0; t < 4; t++){
      int j = g_idx[row*4 + t];
      float coef = g_cval[row*4 + t] * dci * g_dc[j];
      mf = fmaf(coef, g_Z1f[j*128 + o],      mf);
      mc = fmaf(coef, g_Z1f[j*128 + 64 + o], mc);
    }
    ps[(sub*4 + r)*130 + o]      = mf;
    ps[(sub*4 + r)*130 + 64 + o] = mc;
  }
  __syncthreads();
  float b1v = bF2[o], b2v = bC2[o];
  float a1[4], a2[4];
  #pragma unroll
  for (int r = 0; r < 4; r++){ a1[r] = b1v; a2[r] = b2v; }
  #pragma unroll 8
  for (int d = 0; d < 64; d++){
    float wa = Wa_[o*65 + d], wb = Wb_[o*65 + d];
    #pragma unroll
    for (int r = 0; r < 4; r++){
      a1[r] = fmaf(wa, ps[(sub*4 + r)*130 + d],      a1[r]);
      a2[r] = fmaf(wb, ps[(sub*4 + r)*130 + 64 + d], a2[r]);
    }
  }
  #pragma unroll
  for (int r = 0; r < 4; r++){
    int row = base + r;
    float zf  = leaky_f(a1[r]);
    float zcf = leaky_f(a2[r]);
    g_zf [row*64 + o] = zf;
    g_zcf[row*64 + o] = zcf;
    __syncthreads();
    red[sub*64 + o] = zcf*zcf;
    __syncthreads();
    for (int off = 32; off > 0; off >>= 1){
      if (o < off) red[sub*64 + o] += red[sub*64 + o + off];
      __syncthreads();
    }
    float mn = sqrtf(red[sub*64] * 0.015625f) + 1e-10f;
    g_Lcf[row*64 + o] = zcf / mn;
  }
}

// ============ 5. stage4: z2t (128) || z2f (128) ============
__global__ __launch_bounds__(256) void k_stage4(const float* __restrict__ WT2, const float* __restrict__ bT2,
                                                const float* __restrict__ WF2, const float* __restrict__ bF2,
                                                const float* __restrict__ WC2, const float* __restrict__ bC2){
  __shared__ __align__(16) float smem[10656];
  int b = blockIdx.x;
  if (b < 128) z2t_role(b, WT2, bT2, WC2, bC2, smem);
  else z2f_role(b - 128, WF2, bF2, WC2, bC2, smem);
}

// ============ gram role ============
__device__ __forceinline__ void gram_role(int mode, int bx, int by, float* smem){
  float* As = smem;
  float* Bs = smem + 1088;
  float* mean = smem + 2176;
  const float *A0, *A1, *B0, *B1; double* out; int cb; int use_mean;
  if (mode == 0){ A0 = g_Lcf; A1 = g_Lct; B0 = g_Lcf; B1 = g_Lct; use_mean = 0; out = g_G; cb = 128; }
  else if (mode == 1){ A0 = g_zt; A1 = 0; B0 = g_zct; B1 = 0; use_mean = 1; out = g_M1; cb = 64; }
  else              { A0 = g_zf; A1 = 0; B0 = g_zcf; B1 = 0; use_mean = 1; out = g_M2; cb = 64; }
  int ci0 = bx * 16, cj0 = by * 16;
  const float* Ap = (ci0 < 64) ? A0 : A1; int ca_off = ci0 & 63;
  const float* Bp = (cj0 < 64) ? B0 : B1; int cb_off = cj0 & 63;
  int tid = threadIdx.x;
  int ty = tid >> 4, tx = tid & 15;
  if (use_mean){
    float s = 0.f;
    for (int r = ty; r < N; r += 16) s += Ap[r*64 + ca_off + tx];
    As[ty*17 + tx] = s;
    __syncthreads();
    if (ty == 0){
      float m = 0.f;
      #pragma unroll
      for (int k = 0; k < 16; k++) m += As[k*17 + tx];
      mean[tx] = m / (float)N;
    }
    __syncthreads();
  }
  double acc = 0.0; float f = 0.f;
  for (int n0 = 0; n0 < N; n0 += 64){
    __syncthreads();
    #pragma unroll
    for (int e = tid; e < 1024; e += 256){
      int r = n0 + (e >> 4);
      float av = Ap[r*64 + ca_off + (e & 15)];
      if (use_mean) av -= mean[e & 15];
      As[(e >> 4)*17 + (e & 15)] = av;
      Bs[(e >> 4)*17 + (e & 15)] = Bp[r*64 + cb_off + (e & 15)];
    }
    __syncthreads();
    #pragma unroll 16
    for (int r2 = 0; r2 < 64; r2++) f = fmaf(As[r2*17 + ty], Bs[r2*17 + tx], f);
    if (((n0 >> 6) & 1) == 1){ acc += (double)f; f = 0.f; }
  }
  out[(ci0 + ty)*cb + cj0 + tx] = acc;
}

__device__ __forceinline__ void att_role(int blk, const float* __restrict__ Wa, const float* __restrict__ ba,
                                         const float* __restrict__ q,  const float* __restrict__ W2,
                                         const float* __restrict__ b2, float* __restrict__ out, float* smem){
  float* Was = smem;
  float* qv  = smem + 4160;
  float* zsh = smem + 4224;
  float* red = smem + 4992;
  float* sv  = smem + 5248;
  float* av  = smem + 5260;
  float* zag = smem + 5272;
  int tid = threadIdx.x; int sub = tid >> 6; int o = tid & 63;
  for (int e = tid; e < 4096; e += 256) Was[(e>>6)*65 + (e&63)] = Wa[e];
  if (tid < 64) qv[tid] = q[tid];
  __syncthreads();
  for (int r = 0; r < 4; r++){
    int row = blk*16 + sub*4 + r;
    float zfv  = g_zf [row*64 + o];
    float ztv  = g_zt [row*64 + o];
    float zcv  = 0.5f*(g_zcf[row*64 + o] + g_zct[row*64 + o]);
    zsh[(sub*3 + 0)*64 + o] = zfv;
    zsh[(sub*3 + 1)*64 + o] = ztv;
    zsh[(sub*3 + 2)*64 + o] = zcv;
    __syncthreads();
    #pragma unroll
    for (int kk = 0; kk < 3; kk++){
      float t = ba[o];
      #pragma unroll 16
      for (int d = 0; d < 64; d++) t = fmaf(Was[o*65 + d], zsh[(sub*3 + kk)*64 + d], t);
      t = tanhf(t) * qv[o];
      red[sub*64 + o] = t;
      __syncthreads();
      if (o < 32) red[sub*64 + o] += red[sub*64 + o + 32];
      __syncthreads();
      if (o < 32){
        float s = red[sub*64 + o];
        for (int off = 16; off > 0; off >>= 1) s += __shfl_down_sync(0xffffffffu, s, off);
        if (o == 0) sv[sub*3 + kk] = s;
      }
      __syncthreads();
    }
    if (o == 0){
      float m = fmaxf(sv[sub*3], fmaxf(sv[sub*3+1], sv[sub*3+2]));
      float e0 = expf(sv[sub*3]-m), e1 = expf(sv[sub*3+1]-m), e2 = expf(sv[sub*3+2]-m);
      float inv = 1.f/(e0+e1+e2);
      av[sub*3] = e0*inv; av[sub*3+1] = e1*inv; av[sub*3+2] = e2*inv;
    }
    __syncthreads();
    zag[sub*64 + o] = av[sub*3]*zfv + av[sub*3+1]*ztv + av[sub*3+2]*zcv;
    __syncthreads();
    if (o < 7){
      float v = b2[o];
      #pragma unroll 16
      for (int d = 0; d < 64; d++) v = fmaf(W2[o*64 + d], zag[sub*64 + d], v);
      out[row*7 + o] = v;
    }
    __syncthreads();
  }
}

// ============ 6. stage5: gram x3 (96) || att (128), fused final ============
__global__ __launch_bounds__(256) void k_stage5(const float* __restrict__ Wa, const float* __restrict__ ba,
                                                const float* __restrict__ q,  const float* __restrict__ W2,
                                                const float* __restrict__ b2, float* __restrict__ out){
  __shared__ __align__(16) float smem[5536];
  __shared__ unsigned int s_last;
  int b = blockIdx.x;
  int tid = threadIdx.x;
  if (b < 96){
    if (b < 64)      gram_role(0, b >> 3, b & 7, smem);
    else if (b < 80) gram_role(1, (b - 64) >> 2, (b - 64) & 3, smem);
    else             gram_role(2, (b - 80) >> 2, (b - 80) & 3, smem);
    __threadfence();
    __syncthreads();
    if (tid == 0) s_last = (atomicAdd(&g_ticket, 1u) == 95u) ? 1u : 0u;
    __syncthreads();
    if (s_last){
      if (tid == 0) g_ticket = 0u;
      __threadfence();
      double lc = 0.0, ld = 0.0;
      for (int e = tid; e < 128*128; e += 256){
        int a = e >> 7, bb = e & 127;
        double s = ((a < 64) == (bb < 64)) ? 1.0 : -1.0;
        double g = g_G[e];
        lc += s * g * g;
      }
      for (int e = tid; e < 64*64; e += 256){
        double m1 = g_M1[e]; ld += m1*m1;
        double m2 = g_M2[e]; ld += m2*m2;
      }
      double* s1 = (double*)smem;
      double* s2 = s1 + 256;
      s1[tid] = lc; s2[tid] = ld; __syncthreads();
      for (int o = 128; o > 0; o >>= 1){
        if (tid < o){ s1[tid] += s1[tid + o]; s2[tid] += s2[tid + o]; }
        __syncthreads();
      }
      if (tid == 0){
        out[N*7]     = (float)(s1[0] / ((double)N * (double)N));
        out[N*7 + 1] = (float)(s2[0] / (2047.0 * 2047.0));
      }
    }
  } else {
    att_role(b - 96, Wa, ba, q, W2, b2, out, smem);
  }
}

extern "C" void kernel_launch(void* const* d_in, const int* in_sizes, int n_in,
                              void* d_out, int out_size){
  const float* x   = (const float*)d_in[0];
  const float* A   = (const float*)d_in[1];
  const float* W1  = (const float*)d_in[3];
  const float* b1  = (const float*)d_in[4];
  const float* WF1 = (const float*)d_in[5];
  const float* bF1 = (const float*)d_in[6];
  const float* WF2 = (const float*)d_in[7];
  const float* bF2 = (const float*)d_in[8];
  const float* WT1 = (const float*)d_in[9];
  const float* bT1 = (const float*)d_in[10];
  const float* WT2 = (const float*)d_in[11];
  const float* bT2 = (const float*)d_in[12];
  const float* WC1 = (const float*)d_in[13];
  const float* bC1 = (const float*)d_in[14];
  const float* WC2 = (const float*)d_in[15];
  const float* bC2 = (const float*)d_in[16];
  const float* Wa  = (const float*)d_in[17];
  const float* ba  = (const float*)d_in[18];
  const float* q   = (const float*)d_in[19];
  const float* W2  = (const float*)d_in[20];
  const float* b2  = (const float*)d_in[21];
  float* out = (float*)d_out;

  k_pre   <<<N/16, 256>>>(A, x, W1, b1);
  k_stage1<<<768,  256>>>();
  k_stage2<<<320,  256>>>(WT1, bT1, WC1, bC1);
  k_stage3<<<320,  256>>>(WF1, bF1, WC1, bC1);
  k_stage4<<<256,  256>>>(WT2, bT2, WF2, bF2, WC2, bC2);
  k_stage5<<<224,  256>>>(Wa, ba, q, W2, b2, out);
}